// round 1
// baseline (speedup 1.0000x reference)
#include <cuda_runtime.h>
#include <math.h>

#define BB 2
#define SS 2048
#define HH 2048
#define NH 16
#define NKV 4
#define HD 128

// ---------------- scratch (device globals: allocation-free) ----------------
__device__ float g_q[(size_t)BB * SS * NH * HD];    // [4096][2048]
__device__ float g_k[(size_t)BB * SS * NKV * HD];   // [4096][512]
__device__ float g_v[(size_t)BB * SS * NKV * HD];   // [4096][512]
__device__ float g_attn[(size_t)BB * SS * NH * HD]; // [4096][2048]

// ---------------------------------------------------------------------------
// NT SGEMM: C[M][N] = A[M][K] * B[N][K]^T   (both row-major, K contiguous)
// BM=BN=128, BK=16, 256 threads, 8x8 micro-tile (strided by 16).
// ---------------------------------------------------------------------------
__global__ void __launch_bounds__(256) sgemm_nt(
    const float* __restrict__ A, const float* __restrict__ Bw,
    float* __restrict__ C, int M, int N, int K)
{
    __shared__ float Ast[16][129];
    __shared__ float Bst[16][129];

    const int t  = threadIdx.x;
    const int tx = t & 15;
    const int ty = t >> 4;
    const int bm = blockIdx.y * 128;
    const int bn = blockIdx.x * 128;

    float acc[8][8];
#pragma unroll
    for (int i = 0; i < 8; i++)
#pragma unroll
        for (int j = 0; j < 8; j++) acc[i][j] = 0.0f;

    for (int k0 = 0; k0 < K; k0 += 16) {
#pragma unroll
        for (int i = 0; i < 2; i++) {
            int idx = t + i * 256;
            int row = idx >> 2;          // 0..127
            int ks  = (idx & 3) * 4;     // 0,4,8,12
            float4 va = *(const float4*)&A[(size_t)(bm + row) * K + k0 + ks];
            Ast[ks + 0][row] = va.x; Ast[ks + 1][row] = va.y;
            Ast[ks + 2][row] = va.z; Ast[ks + 3][row] = va.w;
            float4 vb = *(const float4*)&Bw[(size_t)(bn + row) * K + k0 + ks];
            Bst[ks + 0][row] = vb.x; Bst[ks + 1][row] = vb.y;
            Bst[ks + 2][row] = vb.z; Bst[ks + 3][row] = vb.w;
        }
        __syncthreads();

#pragma unroll
        for (int k = 0; k < 16; k++) {
            float a[8], b[8];
#pragma unroll
            for (int i = 0; i < 8; i++) a[i] = Ast[k][ty + 16 * i];
#pragma unroll
            for (int j = 0; j < 8; j++) b[j] = Bst[k][tx + 16 * j];
#pragma unroll
            for (int i = 0; i < 8; i++)
#pragma unroll
                for (int j = 0; j < 8; j++) acc[i][j] += a[i] * b[j];
        }
        __syncthreads();
    }

#pragma unroll
    for (int i = 0; i < 8; i++)
#pragma unroll
        for (int j = 0; j < 8; j++)
            C[(size_t)(bm + ty + 16 * i) * N + bn + tx + 16 * j] = acc[i][j];
}

// ---------------------------------------------------------------------------
// Fused per-head RMSNorm + RoPE (in place).
// grid = (B*S rows, nheads), block = 128 (one thread per dim).
// ---------------------------------------------------------------------------
__global__ void rmsnorm_rope(float* __restrict__ x, const float* __restrict__ w,
                             int nheads)
{
    const int row = blockIdx.x;          // b*S + s
    const int h   = blockIdx.y;
    const int s   = row & (SS - 1);
    const int d   = threadIdx.x;         // 0..127

    float* xp = x + ((size_t)row * nheads + h) * HD;
    float val = xp[d];

    float ss = val * val;
#pragma unroll
    for (int off = 16; off > 0; off >>= 1)
        ss += __shfl_xor_sync(0xffffffffu, ss, off);

    __shared__ float red[4];
    __shared__ float xs[128];
    const int warp = d >> 5, lane = d & 31;
    if (lane == 0) red[warp] = ss;
    __syncthreads();
    float tot = red[0] + red[1] + red[2] + red[3];
    float xn  = val * rsqrtf(tot * (1.0f / 128.0f) + 1e-5f) * w[d];
    xs[d] = xn;
    __syncthreads();

    const int i = d & 63;
    // inv_freq = 500000 ^ (-i/64);  ln(500000) = 13.122363377404328
    float inv_freq = expf(-(float)i * (13.122363377404328f / 64.0f));
    float ang = (float)s * inv_freq;
    float sn, cs;
    sincosf(ang, &sn, &cs);

    float other = xs[d ^ 64];
    float res = (d < 64) ? (xn * cs - other * sn) : (xn * cs + other * sn);
    xp[d] = res;
}

// ---------------------------------------------------------------------------
// fp32 causal flash attention with GQA.
// grid = (S/64, NH, B), block = 256. BM=BN=64, D=128.
// Thread (ry, kx): rows {ry+16i}, keys {kx+16m} (strided -> conflict-free smem).
// smem rows padded to 132 floats.
// ---------------------------------------------------------------------------
#define FL_STRIDE 132
#define FL_SMEM_FLOATS (3 * 64 * FL_STRIDE + 64 * 65)

__global__ void __launch_bounds__(256) flash_attn(
    const float* __restrict__ q, const float* __restrict__ k,
    const float* __restrict__ v, float* __restrict__ o)
{
    extern __shared__ float sm[];
    float* Qs = sm;                        // 64 x 132
    float* Ks = Qs + 64 * FL_STRIDE;       // 64 x 132
    float* Vs = Ks + 64 * FL_STRIDE;       // 64 x 132
    float* Ps = Vs + 64 * FL_STRIDE;       // 64 x 65

    const int t  = threadIdx.x;
    const int kx = t & 15;
    const int ry = t >> 4;
    const int qb = blockIdx.x;
    const int h  = blockIdx.y;
    const int b  = blockIdx.z;
    const int kvh = h >> 2;

    const float RSCALE = 0.08838834764831845f; // 1/sqrt(128)

    const float* qbase = q + ((size_t)(b * SS + qb * 64)) * (NH * HD) + h * HD;

    // load Q tile (64 x 128)
#pragma unroll
    for (int i = 0; i < 8; i++) {
        int idx = t + i * 256;
        int r = idx >> 5;
        int ds = (idx & 31) * 4;
        *(float4*)&Qs[r * FL_STRIDE + ds] =
            *(const float4*)&qbase[(size_t)r * (NH * HD) + ds];
    }

    float m_i[4], l_i[4], acc[4][8];
#pragma unroll
    for (int i = 0; i < 4; i++) {
        m_i[i] = -INFINITY; l_i[i] = 0.0f;
#pragma unroll
        for (int j = 0; j < 8; j++) acc[i][j] = 0.0f;
    }

    for (int kb = 0; kb <= qb; kb++) {
        const float* kbase = k + ((size_t)(b * SS + kb * 64)) * (NKV * HD) + kvh * HD;
        const float* vbase = v + ((size_t)(b * SS + kb * 64)) * (NKV * HD) + kvh * HD;
#pragma unroll
        for (int i = 0; i < 8; i++) {
            int idx = t + i * 256;
            int r = idx >> 5;
            int ds = (idx & 31) * 4;
            *(float4*)&Ks[r * FL_STRIDE + ds] =
                *(const float4*)&kbase[(size_t)r * (NKV * HD) + ds];
            *(float4*)&Vs[r * FL_STRIDE + ds] =
                *(const float4*)&vbase[(size_t)r * (NKV * HD) + ds];
        }
        __syncthreads();

        // ---- scores: 4 rows x 4 keys per thread ----
        float sc[4][4];
#pragma unroll
        for (int i = 0; i < 4; i++)
#pragma unroll
            for (int m = 0; m < 4; m++) sc[i][m] = 0.0f;

#pragma unroll 4
        for (int d4 = 0; d4 < 32; d4++) {
            float4 q4[4], k4[4];
#pragma unroll
            for (int i = 0; i < 4; i++)
                q4[i] = *(const float4*)&Qs[(ry + 16 * i) * FL_STRIDE + d4 * 4];
#pragma unroll
            for (int m = 0; m < 4; m++)
                k4[m] = *(const float4*)&Ks[(kx + 16 * m) * FL_STRIDE + d4 * 4];
#pragma unroll
            for (int i = 0; i < 4; i++)
#pragma unroll
                for (int m = 0; m < 4; m++) {
                    sc[i][m] += q4[i].x * k4[m].x + q4[i].y * k4[m].y
                              + q4[i].z * k4[m].z + q4[i].w * k4[m].w;
                }
        }

        const bool diag = (kb == qb);
#pragma unroll
        for (int i = 0; i < 4; i++) {
            const int rr = ry + 16 * i;
            float mt = -INFINITY;
#pragma unroll
            for (int m = 0; m < 4; m++) {
                float sv = sc[i][m] * RSCALE;
                if (diag && (kx + 16 * m) > rr) sv = -INFINITY;
                sc[i][m] = sv;
                mt = fmaxf(mt, sv);
            }
#pragma unroll
            for (int off = 8; off > 0; off >>= 1)
                mt = fmaxf(mt, __shfl_xor_sync(0xffffffffu, mt, off, 16));

            float mnew  = fmaxf(m_i[i], mt);
            float scale = __expf(m_i[i] - mnew);
            float psum  = 0.0f;
#pragma unroll
            for (int m = 0; m < 4; m++) {
                float p = __expf(sc[i][m] - mnew);
                Ps[rr * 65 + kx + 16 * m] = p;
                psum += p;
            }
#pragma unroll
            for (int off = 8; off > 0; off >>= 1)
                psum += __shfl_xor_sync(0xffffffffu, psum, off, 16);

            l_i[i] = l_i[i] * scale + psum;
            m_i[i] = mnew;
#pragma unroll
            for (int j = 0; j < 8; j++) acc[i][j] *= scale;
        }
        __syncthreads();

        // ---- PV: dims {4kx..4kx+3} and {64+4kx..64+4kx+3} ----
#pragma unroll 4
        for (int j = 0; j < 64; j++) {
            float4 v0 = *(const float4*)&Vs[j * FL_STRIDE + kx * 4];
            float4 v1 = *(const float4*)&Vs[j * FL_STRIDE + 64 + kx * 4];
#pragma unroll
            for (int i = 0; i < 4; i++) {
                float p = Ps[(ry + 16 * i) * 65 + j];
                acc[i][0] += p * v0.x; acc[i][1] += p * v0.y;
                acc[i][2] += p * v0.z; acc[i][3] += p * v0.w;
                acc[i][4] += p * v1.x; acc[i][5] += p * v1.y;
                acc[i][6] += p * v1.z; acc[i][7] += p * v1.w;
            }
        }
        __syncthreads();
    }

    float* obase = o + ((size_t)(b * SS + qb * 64)) * (NH * HD) + h * HD;
#pragma unroll
    for (int i = 0; i < 4; i++) {
        float inv = 1.0f / l_i[i];
        int r = ry + 16 * i;
        float4 r0 = make_float4(acc[i][0] * inv, acc[i][1] * inv,
                                acc[i][2] * inv, acc[i][3] * inv);
        float4 r1 = make_float4(acc[i][4] * inv, acc[i][5] * inv,
                                acc[i][6] * inv, acc[i][7] * inv);
        *(float4*)&obase[(size_t)r * (NH * HD) + kx * 4] = r0;
        *(float4*)&obase[(size_t)r * (NH * HD) + 64 + kx * 4] = r1;
    }
}

// ---------------------------------------------------------------------------
extern "C" void kernel_launch(void* const* d_in, const int* in_sizes, int n_in,
                              void* d_out, int out_size)
{
    const float* hs  = (const float*)d_in[0]; // [2,2048,2048]
    const float* q_w = (const float*)d_in[1]; // [2048,2048]
    const float* k_w = (const float*)d_in[2]; // [512,2048]
    const float* v_w = (const float*)d_in[3]; // [512,2048]
    const float* o_w = (const float*)d_in[4]; // [2048,2048]
    const float* qn  = (const float*)d_in[5]; // [128]
    const float* kn  = (const float*)d_in[6]; // [128]
    float* out = (float*)d_out;

    float *pq, *pk, *pv, *pa;
    cudaGetSymbolAddress((void**)&pq, g_q);
    cudaGetSymbolAddress((void**)&pk, g_k);
    cudaGetSymbolAddress((void**)&pv, g_v);
    cudaGetSymbolAddress((void**)&pa, g_attn);

    const int M = BB * SS;     // 4096
    const int K = HH;          // 2048

    // QKV projections
    sgemm_nt<<<dim3((NH * HD) / 128, M / 128), 256>>>(hs, q_w, pq, M, NH * HD, K);
    sgemm_nt<<<dim3((NKV * HD) / 128, M / 128), 256>>>(hs, k_w, pk, M, NKV * HD, K);
    sgemm_nt<<<dim3((NKV * HD) / 128, M / 128), 256>>>(hs, v_w, pv, M, NKV * HD, K);

    // RMSNorm + RoPE
    rmsnorm_rope<<<dim3(M, NH), 128>>>(pq, qn, NH);
    rmsnorm_rope<<<dim3(M, NKV), 128>>>(pk, kn, NKV);

    // causal flash attention (GQA)
    size_t smem = FL_SMEM_FLOATS * sizeof(float);
    cudaFuncSetAttribute(flash_attn, cudaFuncAttributeMaxDynamicSharedMemorySize,
                         (int)smem);
    flash_attn<<<dim3(SS / 64, NH, BB), 256, smem>>>(pq, pk, pv, pa);

    // output projection
    sgemm_nt<<<dim3(HH / 128, M / 128), 256>>>(pa, o_w, out, M, HH, K);
}

// round 4
// speedup vs baseline: 1.6241x; 1.6241x over previous
#include <cuda_runtime.h>
#include <cuda_bf16.h>
#include <stdint.h>
#include <math.h>

#define BB 2
#define SS 2048
#define HH 2048
#define NH 16
#define NKV 4
#define HD 128

// ---------------- scratch (device globals: allocation-free) ----------------
__device__ float g_q[(size_t)BB * SS * NH * HD];
__device__ float g_k[(size_t)BB * SS * NKV * HD];
__device__ float g_v[(size_t)BB * SS * NKV * HD];
__device__ float g_attn[(size_t)BB * SS * NH * HD];

// ===================== warp-MMA helpers (sm_80+ path, no arch-feature gate) ===
__device__ __forceinline__ uint32_t smem_to_u32(const void* p) {
    uint32_t a;
    asm("{ .reg .u64 t; cvta.to.shared.u64 t, %1; cvt.u32.u64 %0, t; }"
        : "=r"(a) : "l"(p));
    return a;
}
__device__ __forceinline__ void ldsm_x4(uint32_t r[4], uint32_t addr) {
    asm volatile("ldmatrix.sync.aligned.m8n8.x4.shared.b16 {%0,%1,%2,%3}, [%4];"
                 : "=r"(r[0]), "=r"(r[1]), "=r"(r[2]), "=r"(r[3]) : "r"(addr));
}
__device__ __forceinline__ void mma16816(float c[4], const uint32_t a[4],
                                         const uint32_t b0, const uint32_t b1) {
    asm volatile(
        "mma.sync.aligned.m16n8k16.row.col.f32.bf16.bf16.f32 "
        "{%0,%1,%2,%3}, {%4,%5,%6,%7}, {%8,%9}, {%0,%1,%2,%3};"
        : "+f"(c[0]), "+f"(c[1]), "+f"(c[2]), "+f"(c[3])
        : "r"(a[0]), "r"(a[1]), "r"(a[2]), "r"(a[3]), "r"(b0), "r"(b1));
}

// split fp32 -> (hi, lo) bf16 pairs, 8 values -> 2 uint4
__device__ __forceinline__ void split8(float4 x, float4 y, uint4& hi, uint4& lo) {
    float f[8] = {x.x, x.y, x.z, x.w, y.x, y.y, y.z, y.w};
    uint32_t h[8], l[8];
#pragma unroll
    for (int i = 0; i < 8; i++) {
        __nv_bfloat16 hb = __float2bfloat16_rn(f[i]);
        float r = f[i] - __bfloat162float(hb);
        __nv_bfloat16 lb = __float2bfloat16_rn(r);
        h[i] = (uint32_t)__bfloat16_as_ushort(hb);
        l[i] = (uint32_t)__bfloat16_as_ushort(lb);
    }
    hi.x = h[0] | (h[1] << 16); hi.y = h[2] | (h[3] << 16);
    hi.z = h[4] | (h[5] << 16); hi.w = h[6] | (h[7] << 16);
    lo.x = l[0] | (l[1] << 16); lo.y = l[2] | (l[3] << 16);
    lo.z = l[4] | (l[5] << 16); lo.w = l[6] | (l[7] << 16);
}

// swizzled byte offset within a [128 rows x 32 bf16] tile (64B rows, 4x16B units)
__device__ __forceinline__ uint32_t swz(int row, int c) {
    return (uint32_t)(row * 64 + ((c ^ ((row >> 1) & 3)) << 4));
}

#define SA_HI 0
#define SA_LO 8192
#define SB_HI 16384
#define SB_LO 24576

// ---------------------------------------------------------------------------
// split-bf16 NT GEMM on mma.sync: C[M][N] = A[M][K] * B[N][K]^T  (fp32 I/O)
// BM=BN=128, BK=32, 512 threads (16 warps, 4x4), warp tile 32x32.
// ---------------------------------------------------------------------------
__global__ void __launch_bounds__(512) gemm_tc(
    const float* __restrict__ A, const float* __restrict__ Bw,
    float* __restrict__ C, int M, int N, int K)
{
    __shared__ __align__(16) char smem[32768];
    const uint32_t sb = smem_to_u32(smem);

    const int t = threadIdx.x;
    const int lane = t & 31, wid = t >> 5;
    const int bm = blockIdx.y * 128, bn = blockIdx.x * 128;
    const int wm = (wid & 3) * 32;   // warp row base within tile
    const int wn = (wid >> 2) * 32;  // warp col base within tile

    // global->smem staging map: thread t handles (row = t>>2, unit c = t&3)
    const int lrow = t >> 2, lc = t & 3;
    const float* gA = A + (size_t)(bm + lrow) * K + lc * 8;
    const float* gB = Bw + (size_t)(bn + lrow) * K + lc * 8;
    const uint32_t st = swz(lrow, lc);

    float acc[2][4][4];
#pragma unroll
    for (int i = 0; i < 2; i++)
#pragma unroll
        for (int j = 0; j < 4; j++)
#pragma unroll
            for (int q = 0; q < 4; q++) acc[i][j][q] = 0.0f;

    float4 pa0 = *(const float4*)gA;
    float4 pa1 = *(const float4*)(gA + 4);
    float4 pb0 = *(const float4*)gB;
    float4 pb1 = *(const float4*)(gB + 4);

    const int nch = K >> 5;   // chunks of BK=32
    for (int ch = 0; ch < nch; ch++) {
        uint4 ahi, alo, bhi, blo;
        split8(pa0, pa1, ahi, alo);
        split8(pb0, pb1, bhi, blo);
        __syncthreads();   // previous chunk's compute done
        *(uint4*)(smem + SA_HI + st) = ahi;
        *(uint4*)(smem + SA_LO + st) = alo;
        *(uint4*)(smem + SB_HI + st) = bhi;
        *(uint4*)(smem + SB_LO + st) = blo;
        __syncthreads();

        if (ch + 1 < nch) {
            gA += 32; gB += 32;
            pa0 = *(const float4*)gA;
            pa1 = *(const float4*)(gA + 4);
            pb0 = *(const float4*)gB;
            pb1 = *(const float4*)(gB + 4);
        }

#pragma unroll
        for (int ks = 0; ks < 2; ks++) {
            uint32_t ah[2][4], al[2][4];
#pragma unroll
            for (int mt = 0; mt < 2; mt++) {
                int row = wm + mt * 16 + (lane & 15);
                int c = ks * 2 + (lane >> 4);
                uint32_t off = swz(row, c);
                ldsm_x4(ah[mt], sb + SA_HI + off);
                ldsm_x4(al[mt], sb + SA_LO + off);
            }
            uint32_t bh[2][4], bl[2][4];
#pragma unroll
            for (int np = 0; np < 2; np++) {
                int row = wn + np * 16 + (lane & 7) + ((lane >> 4) & 1) * 8;
                int c = ks * 2 + ((lane >> 3) & 1);
                uint32_t off = swz(row, c);
                ldsm_x4(bh[np], sb + SB_HI + off);
                ldsm_x4(bl[np], sb + SB_LO + off);
            }
#pragma unroll
            for (int mt = 0; mt < 2; mt++)
#pragma unroll
                for (int nt = 0; nt < 4; nt++) {
                    const int np = nt >> 1, pb = (nt & 1) * 2;
                    mma16816(acc[mt][nt], ah[mt], bh[np][pb], bh[np][pb + 1]);
                    mma16816(acc[mt][nt], ah[mt], bl[np][pb], bl[np][pb + 1]);
                    mma16816(acc[mt][nt], al[mt], bh[np][pb], bh[np][pb + 1]);
                }
        }
    }

    // epilogue: direct fragment stores (float2)
#pragma unroll
    for (int mt = 0; mt < 2; mt++)
#pragma unroll
        for (int nt = 0; nt < 4; nt++) {
            int r0 = bm + wm + mt * 16 + (lane >> 2);
            int c0 = bn + wn + nt * 8 + (lane & 3) * 2;
            float2 v0 = make_float2(acc[mt][nt][0], acc[mt][nt][1]);
            float2 v1 = make_float2(acc[mt][nt][2], acc[mt][nt][3]);
            *(float2*)&C[(size_t)r0 * N + c0] = v0;
            *(float2*)&C[(size_t)(r0 + 8) * N + c0] = v1;
        }
}

// ---------------------------------------------------------------------------
// Fused per-head RMSNorm + RoPE (in place).
// ---------------------------------------------------------------------------
__global__ void rmsnorm_rope(float* __restrict__ x, const float* __restrict__ w,
                             int nheads)
{
    const int row = blockIdx.x;
    const int h   = blockIdx.y;
    const int s   = row & (SS - 1);
    const int d   = threadIdx.x;

    float* xp = x + ((size_t)row * nheads + h) * HD;
    float val = xp[d];

    float ss = val * val;
#pragma unroll
    for (int off = 16; off > 0; off >>= 1)
        ss += __shfl_xor_sync(0xffffffffu, ss, off);

    __shared__ float red[4];
    __shared__ float xs[128];
    const int warp = d >> 5, lane = d & 31;
    if (lane == 0) red[warp] = ss;
    __syncthreads();
    float tot = red[0] + red[1] + red[2] + red[3];
    float xn  = val * rsqrtf(tot * (1.0f / 128.0f) + 1e-5f) * w[d];
    xs[d] = xn;
    __syncthreads();

    const int i = d & 63;
    float inv_freq = expf(-(float)i * (13.122363377404328f / 64.0f));
    float ang = (float)s * inv_freq;
    float sn, cs;
    sincosf(ang, &sn, &cs);

    float other = xs[d ^ 64];
    float res = (d < 64) ? (xn * cs - other * sn) : (xn * cs + other * sn);
    xp[d] = res;
}

// ---------------------------------------------------------------------------
// fp32 causal flash attention with GQA.
// ---------------------------------------------------------------------------
#define FL_STRIDE 132
#define FL_SMEM_FLOATS (3 * 64 * FL_STRIDE + 64 * 65)

__global__ void __launch_bounds__(256) flash_attn(
    const float* __restrict__ q, const float* __restrict__ k,
    const float* __restrict__ v, float* __restrict__ o)
{
    extern __shared__ float sm[];
    float* Qs = sm;
    float* Ks = Qs + 64 * FL_STRIDE;
    float* Vs = Ks + 64 * FL_STRIDE;
    float* Ps = Vs + 64 * FL_STRIDE;

    const int t  = threadIdx.x;
    const int kx = t & 15;
    const int ry = t >> 4;
    const int qb = blockIdx.x;
    const int h  = blockIdx.y;
    const int b  = blockIdx.z;
    const int kvh = h >> 2;

    const float RSCALE = 0.08838834764831845f;

    const float* qbase = q + ((size_t)(b * SS + qb * 64)) * (NH * HD) + h * HD;

#pragma unroll
    for (int i = 0; i < 8; i++) {
        int idx = t + i * 256;
        int r = idx >> 5;
        int ds = (idx & 31) * 4;
        *(float4*)&Qs[r * FL_STRIDE + ds] =
            *(const float4*)&qbase[(size_t)r * (NH * HD) + ds];
    }

    float m_i[4], l_i[4], acc[4][8];
#pragma unroll
    for (int i = 0; i < 4; i++) {
        m_i[i] = -INFINITY; l_i[i] = 0.0f;
#pragma unroll
        for (int j = 0; j < 8; j++) acc[i][j] = 0.0f;
    }

    for (int kb = 0; kb <= qb; kb++) {
        const float* kbase = k + ((size_t)(b * SS + kb * 64)) * (NKV * HD) + kvh * HD;
        const float* vbase = v + ((size_t)(b * SS + kb * 64)) * (NKV * HD) + kvh * HD;
#pragma unroll
        for (int i = 0; i < 8; i++) {
            int idx = t + i * 256;
            int r = idx >> 5;
            int ds = (idx & 31) * 4;
            *(float4*)&Ks[r * FL_STRIDE + ds] =
                *(const float4*)&kbase[(size_t)r * (NKV * HD) + ds];
            *(float4*)&Vs[r * FL_STRIDE + ds] =
                *(const float4*)&vbase[(size_t)r * (NKV * HD) + ds];
        }
        __syncthreads();

        float sc[4][4];
#pragma unroll
        for (int i = 0; i < 4; i++)
#pragma unroll
            for (int m = 0; m < 4; m++) sc[i][m] = 0.0f;

#pragma unroll 4
        for (int d4 = 0; d4 < 32; d4++) {
            float4 q4[4], k4[4];
#pragma unroll
            for (int i = 0; i < 4; i++)
                q4[i] = *(const float4*)&Qs[(ry + 16 * i) * FL_STRIDE + d4 * 4];
#pragma unroll
            for (int m = 0; m < 4; m++)
                k4[m] = *(const float4*)&Ks[(kx + 16 * m) * FL_STRIDE + d4 * 4];
#pragma unroll
            for (int i = 0; i < 4; i++)
#pragma unroll
                for (int m = 0; m < 4; m++) {
                    sc[i][m] += q4[i].x * k4[m].x + q4[i].y * k4[m].y
                              + q4[i].z * k4[m].z + q4[i].w * k4[m].w;
                }
        }

        const bool diag = (kb == qb);
#pragma unroll
        for (int i = 0; i < 4; i++) {
            const int rr = ry + 16 * i;
            float mt = -INFINITY;
#pragma unroll
            for (int m = 0; m < 4; m++) {
                float sv = sc[i][m] * RSCALE;
                if (diag && (kx + 16 * m) > rr) sv = -INFINITY;
                sc[i][m] = sv;
                mt = fmaxf(mt, sv);
            }
#pragma unroll
            for (int off = 8; off > 0; off >>= 1)
                mt = fmaxf(mt, __shfl_xor_sync(0xffffffffu, mt, off, 16));

            float mnew  = fmaxf(m_i[i], mt);
            float scale = __expf(m_i[i] - mnew);
            float psum  = 0.0f;
#pragma unroll
            for (int m = 0; m < 4; m++) {
                float p = __expf(sc[i][m] - mnew);
                Ps[rr * 65 + kx + 16 * m] = p;
                psum += p;
            }
#pragma unroll
            for (int off = 8; off > 0; off >>= 1)
                psum += __shfl_xor_sync(0xffffffffu, psum, off, 16);

            l_i[i] = l_i[i] * scale + psum;
            m_i[i] = mnew;
#pragma unroll
            for (int j = 0; j < 8; j++) acc[i][j] *= scale;
        }
        __syncthreads();

#pragma unroll 4
        for (int j = 0; j < 64; j++) {
            float4 v0 = *(const float4*)&Vs[j * FL_STRIDE + kx * 4];
            float4 v1 = *(const float4*)&Vs[j * FL_STRIDE + 64 + kx * 4];
#pragma unroll
            for (int i = 0; i < 4; i++) {
                float p = Ps[(ry + 16 * i) * 65 + j];
                acc[i][0] += p * v0.x; acc[i][1] += p * v0.y;
                acc[i][2] += p * v0.z; acc[i][3] += p * v0.w;
                acc[i][4] += p * v1.x; acc[i][5] += p * v1.y;
                acc[i][6] += p * v1.z; acc[i][7] += p * v1.w;
            }
        }
        __syncthreads();
    }

    float* obase = o + ((size_t)(b * SS + qb * 64)) * (NH * HD) + h * HD;
#pragma unroll
    for (int i = 0; i < 4; i++) {
        float inv = 1.0f / l_i[i];
        int r = ry + 16 * i;
        float4 r0 = make_float4(acc[i][0] * inv, acc[i][1] * inv,
                                acc[i][2] * inv, acc[i][3] * inv);
        float4 r1 = make_float4(acc[i][4] * inv, acc[i][5] * inv,
                                acc[i][6] * inv, acc[i][7] * inv);
        *(float4*)&obase[(size_t)r * (NH * HD) + kx * 4] = r0;
        *(float4*)&obase[(size_t)r * (NH * HD) + 64 + kx * 4] = r1;
    }
}

// ---------------------------------------------------------------------------
extern "C" void kernel_launch(void* const* d_in, const int* in_sizes, int n_in,
                              void* d_out, int out_size)
{
    const float* hs  = (const float*)d_in[0];
    const float* q_w = (const float*)d_in[1];
    const float* k_w = (const float*)d_in[2];
    const float* v_w = (const float*)d_in[3];
    const float* o_w = (const float*)d_in[4];
    const float* qn  = (const float*)d_in[5];
    const float* kn  = (const float*)d_in[6];
    float* out = (float*)d_out;

    float *pq, *pk, *pv, *pa;
    cudaGetSymbolAddress((void**)&pq, g_q);
    cudaGetSymbolAddress((void**)&pk, g_k);
    cudaGetSymbolAddress((void**)&pv, g_v);
    cudaGetSymbolAddress((void**)&pa, g_attn);

    const int M = BB * SS;     // 4096
    const int K = HH;          // 2048

    // QKV projections (split-bf16 mma.sync)
    gemm_tc<<<dim3((NH * HD) / 128, M / 128), 512>>>(hs, q_w, pq, M, NH * HD, K);
    gemm_tc<<<dim3((NKV * HD) / 128, M / 128), 512>>>(hs, k_w, pk, M, NKV * HD, K);
    gemm_tc<<<dim3((NKV * HD) / 128, M / 128), 512>>>(hs, v_w, pv, M, NKV * HD, K);

    // RMSNorm + RoPE
    rmsnorm_rope<<<dim3(M, NH), 128>>>(pq, qn, NH);
    rmsnorm_rope<<<dim3(M, NKV), 128>>>(pk, kn, NKV);

    // causal flash attention (GQA)
    size_t smem = FL_SMEM_FLOATS * sizeof(float);
    cudaFuncSetAttribute(flash_attn, cudaFuncAttributeMaxDynamicSharedMemorySize,
                         (int)smem);
    flash_attn<<<dim3(SS / 64, NH, BB), 256, smem>>>(pq, pk, pv, pa);

    // output projection
    gemm_tc<<<dim3(HH / 128, M / 128), 512>>>(pa, o_w, out, M, HH, K);
}

// round 5
// speedup vs baseline: 2.4789x; 1.5263x over previous
#include <cuda_runtime.h>
#include <cuda_bf16.h>
#include <stdint.h>
#include <math.h>

#define BB 2
#define SS 2048
#define HH 2048
#define NH 16
#define NKV 4
#define HD 128

// ---------------- scratch (device globals: allocation-free) ----------------
__device__ float g_q[(size_t)BB * SS * NH * HD];
__device__ float g_k[(size_t)BB * SS * NKV * HD];
__device__ float g_v[(size_t)BB * SS * NKV * HD];
__device__ float g_attn[(size_t)BB * SS * NH * HD];
__device__ __nv_bfloat16 g_qhi[(size_t)BB * SS * NH * HD];
__device__ __nv_bfloat16 g_qlo[(size_t)BB * SS * NH * HD];
__device__ __nv_bfloat16 g_khi[(size_t)BB * SS * NKV * HD];
__device__ __nv_bfloat16 g_klo[(size_t)BB * SS * NKV * HD];
__device__ __nv_bfloat16 g_vhi[(size_t)BB * SS * NKV * HD];
__device__ __nv_bfloat16 g_vlo[(size_t)BB * SS * NKV * HD];

// ===================== warp-MMA helpers =====================
__device__ __forceinline__ uint32_t smem_to_u32(const void* p) {
    uint32_t a;
    asm("{ .reg .u64 t; cvta.to.shared.u64 t, %1; cvt.u32.u64 %0, t; }"
        : "=r"(a) : "l"(p));
    return a;
}
__device__ __forceinline__ void ldsm_x4(uint32_t r[4], uint32_t addr) {
    asm volatile("ldmatrix.sync.aligned.m8n8.x4.shared.b16 {%0,%1,%2,%3}, [%4];"
                 : "=r"(r[0]), "=r"(r[1]), "=r"(r[2]), "=r"(r[3]) : "r"(addr));
}
__device__ __forceinline__ void ldsm_x4_t(uint32_t r[4], uint32_t addr) {
    asm volatile("ldmatrix.sync.aligned.m8n8.x4.trans.shared.b16 {%0,%1,%2,%3}, [%4];"
                 : "=r"(r[0]), "=r"(r[1]), "=r"(r[2]), "=r"(r[3]) : "r"(addr));
}
__device__ __forceinline__ void mma16816(float c[4], const uint32_t a[4],
                                         const uint32_t b0, const uint32_t b1) {
    asm volatile(
        "mma.sync.aligned.m16n8k16.row.col.f32.bf16.bf16.f32 "
        "{%0,%1,%2,%3}, {%4,%5,%6,%7}, {%8,%9}, {%0,%1,%2,%3};"
        : "+f"(c[0]), "+f"(c[1]), "+f"(c[2]), "+f"(c[3])
        : "r"(a[0]), "r"(a[1]), "r"(a[2]), "r"(a[3]), "r"(b0), "r"(b1));
}

__device__ __forceinline__ void split2(float x, float y, uint32_t& hi, uint32_t& lo) {
    __nv_bfloat16 hx = __float2bfloat16_rn(x);
    __nv_bfloat16 hy = __float2bfloat16_rn(y);
    __nv_bfloat16 lx = __float2bfloat16_rn(x - __bfloat162float(hx));
    __nv_bfloat16 ly = __float2bfloat16_rn(y - __bfloat162float(hy));
    hi = (uint32_t)__bfloat16_as_ushort(hx) | ((uint32_t)__bfloat16_as_ushort(hy) << 16);
    lo = (uint32_t)__bfloat16_as_ushort(lx) | ((uint32_t)__bfloat16_as_ushort(ly) << 16);
}

// split fp32 -> (hi, lo) bf16 pairs, 8 values -> 2 uint4
__device__ __forceinline__ void split8(float4 x, float4 y, uint4& hi, uint4& lo) {
    split2(x.x, x.y, hi.x, lo.x);
    split2(x.z, x.w, hi.y, lo.y);
    split2(y.x, y.y, hi.z, lo.z);
    split2(y.z, y.w, hi.w, lo.w);
}

// swizzled byte offset in a [rows x 32 bf16] tile (64B rows, 4x16B units)
__device__ __forceinline__ uint32_t swz(int row, int c) {
    return (uint32_t)(row * 64 + ((c ^ ((row >> 1) & 3)) << 4));
}
// swizzled byte offset in a [rows x 128 bf16] tile (256B rows, 16x16B units)
__device__ __forceinline__ uint32_t swz256(int row, int c) {
    return (uint32_t)(row * 256 + ((c ^ (row & 7)) << 4));
}

#define SA_HI 0
#define SA_LO 8192
#define SB_HI 16384
#define SB_LO 24576

// ---------------------------------------------------------------------------
// split-bf16 NT GEMM on mma.sync: C[M][N] = A[M][K] * B[N][K]^T  (fp32 I/O)
// ---------------------------------------------------------------------------
__global__ void __launch_bounds__(512) gemm_tc(
    const float* __restrict__ A, const float* __restrict__ Bw,
    float* __restrict__ C, int M, int N, int K)
{
    __shared__ __align__(16) char smem[32768];
    const uint32_t sb = smem_to_u32(smem);

    const int t = threadIdx.x;
    const int lane = t & 31, wid = t >> 5;
    const int bm = blockIdx.y * 128, bn = blockIdx.x * 128;
    const int wm = (wid & 3) * 32;
    const int wn = (wid >> 2) * 32;

    const int lrow = t >> 2, lc = t & 3;
    const float* gA = A + (size_t)(bm + lrow) * K + lc * 8;
    const float* gB = Bw + (size_t)(bn + lrow) * K + lc * 8;
    const uint32_t st = swz(lrow, lc);

    float acc[2][4][4];
#pragma unroll
    for (int i = 0; i < 2; i++)
#pragma unroll
        for (int j = 0; j < 4; j++)
#pragma unroll
            for (int q = 0; q < 4; q++) acc[i][j][q] = 0.0f;

    float4 pa0 = *(const float4*)gA;
    float4 pa1 = *(const float4*)(gA + 4);
    float4 pb0 = *(const float4*)gB;
    float4 pb1 = *(const float4*)(gB + 4);

    const int nch = K >> 5;
    for (int ch = 0; ch < nch; ch++) {
        uint4 ahi, alo, bhi, blo;
        split8(pa0, pa1, ahi, alo);
        split8(pb0, pb1, bhi, blo);
        __syncthreads();
        *(uint4*)(smem + SA_HI + st) = ahi;
        *(uint4*)(smem + SA_LO + st) = alo;
        *(uint4*)(smem + SB_HI + st) = bhi;
        *(uint4*)(smem + SB_LO + st) = blo;
        __syncthreads();

        if (ch + 1 < nch) {
            gA += 32; gB += 32;
            pa0 = *(const float4*)gA;
            pa1 = *(const float4*)(gA + 4);
            pb0 = *(const float4*)gB;
            pb1 = *(const float4*)(gB + 4);
        }

#pragma unroll
        for (int ks = 0; ks < 2; ks++) {
            uint32_t ah[2][4], al[2][4];
#pragma unroll
            for (int mt = 0; mt < 2; mt++) {
                int row = wm + mt * 16 + (lane & 15);
                int c = ks * 2 + (lane >> 4);
                uint32_t off = swz(row, c);
                ldsm_x4(ah[mt], sb + SA_HI + off);
                ldsm_x4(al[mt], sb + SA_LO + off);
            }
#pragma unroll
            for (int np = 0; np < 2; np++) {
                uint32_t bh[4], bl[4];
                int row = wn + np * 16 + (lane & 7) + ((lane >> 4) & 1) * 8;
                int c = ks * 2 + ((lane >> 3) & 1);
                uint32_t off = swz(row, c);
                ldsm_x4(bh, sb + SB_HI + off);
                ldsm_x4(bl, sb + SB_LO + off);
#pragma unroll
                for (int half = 0; half < 2; half++) {
                    int nt = np * 2 + half, pb = half * 2;
#pragma unroll
                    for (int mt = 0; mt < 2; mt++) {
                        mma16816(acc[mt][nt], ah[mt], bh[pb], bh[pb + 1]);
                        mma16816(acc[mt][nt], ah[mt], bl[pb], bl[pb + 1]);
                        mma16816(acc[mt][nt], al[mt], bh[pb], bh[pb + 1]);
                    }
                }
            }
        }
    }

#pragma unroll
    for (int mt = 0; mt < 2; mt++)
#pragma unroll
        for (int nt = 0; nt < 4; nt++) {
            int r0 = bm + wm + mt * 16 + (lane >> 2);
            int c0 = bn + wn + nt * 8 + (lane & 3) * 2;
            float2 v0 = make_float2(acc[mt][nt][0], acc[mt][nt][1]);
            float2 v1 = make_float2(acc[mt][nt][2], acc[mt][nt][3]);
            *(float2*)&C[(size_t)r0 * N + c0] = v0;
            *(float2*)&C[(size_t)(r0 + 8) * N + c0] = v1;
        }
}

// ---------------------------------------------------------------------------
// Fused per-head RMSNorm + RoPE -> split bf16 hi/lo outputs (optionally pre-scaled).
// ---------------------------------------------------------------------------
__global__ void rmsnorm_rope(const float* __restrict__ x, const float* __restrict__ w,
                             __nv_bfloat16* __restrict__ hi, __nv_bfloat16* __restrict__ lo,
                             int nheads, float prescale)
{
    const int row = blockIdx.x;
    const int h   = blockIdx.y;
    const int s   = row & (SS - 1);
    const int d   = threadIdx.x;

    const size_t base = ((size_t)row * nheads + h) * HD;
    float val = x[base + d];

    float ss = val * val;
#pragma unroll
    for (int off = 16; off > 0; off >>= 1)
        ss += __shfl_xor_sync(0xffffffffu, ss, off);

    __shared__ float red[4];
    __shared__ float xs[128];
    const int warp = d >> 5, lane = d & 31;
    if (lane == 0) red[warp] = ss;
    __syncthreads();
    float tot = red[0] + red[1] + red[2] + red[3];
    float xn  = val * rsqrtf(tot * (1.0f / 128.0f) + 1e-5f) * w[d];
    xs[d] = xn;
    __syncthreads();

    const int i = d & 63;
    float inv_freq = expf(-(float)i * (13.122363377404328f / 64.0f));
    float ang = (float)s * inv_freq;
    float sn, cs;
    sincosf(ang, &sn, &cs);

    float other = xs[d ^ 64];
    float res = (d < 64) ? (xn * cs - other * sn) : (xn * cs + other * sn);
    res *= prescale;

    __nv_bfloat16 hb = __float2bfloat16_rn(res);
    __nv_bfloat16 lb = __float2bfloat16_rn(res - __bfloat162float(hb));
    hi[base + d] = hb;
    lo[base + d] = lb;
}

// ---------------------------------------------------------------------------
// V fp32 -> bf16 hi/lo
// ---------------------------------------------------------------------------
__global__ void v_convert(const float* __restrict__ v,
                          __nv_bfloat16* __restrict__ hi, __nv_bfloat16* __restrict__ lo)
{
    size_t i = (size_t)blockIdx.x * blockDim.x + threadIdx.x;
    float f = v[i];
    __nv_bfloat16 hb = __float2bfloat16_rn(f);
    __nv_bfloat16 lb = __float2bfloat16_rn(f - __bfloat162float(hb));
    hi[i] = hb;
    lo[i] = lb;
}

// ---------------------------------------------------------------------------
// Tensor-core causal flash attention, split-bf16, GQA.
// BM=128, BN=64, D=128. 256 threads = 8 warps; warp tile m16 x n64.
// ---------------------------------------------------------------------------
#define SQ_HI 0
#define SQ_LO 32768
#define SK_HI 65536
#define SK_LO 81920
#define SV_HI 98304
#define SV_LO 114688
#define FL_SMEM 131072

__global__ void __launch_bounds__(256) flash_attn_tc(
    const __nv_bfloat16* __restrict__ qhi, const __nv_bfloat16* __restrict__ qlo,
    const __nv_bfloat16* __restrict__ khi, const __nv_bfloat16* __restrict__ klo,
    const __nv_bfloat16* __restrict__ vhi, const __nv_bfloat16* __restrict__ vlo,
    float* __restrict__ o)
{
    extern __shared__ char smem[];
    const uint32_t sb = smem_to_u32(smem);
    const int t = threadIdx.x, lane = t & 31, wid = t >> 5;
    const int qb = blockIdx.x, h = blockIdx.y, b = blockIdx.z;
    const int kvh = h >> 2;
    const int warp_m = wid * 16;
    const int QSTR = NH * HD;
    const int KSTR = NKV * HD;

    // ---- load Q tile (128 x 128, hi+lo) ----
    {
        const __nv_bfloat16* qh = qhi + ((size_t)(b * SS + qb * 128)) * QSTR + h * HD;
        const __nv_bfloat16* ql = qlo + ((size_t)(b * SS + qb * 128)) * QSTR + h * HD;
#pragma unroll
        for (int i = 0; i < 8; i++) {
            int u = t + i * 256;
            int r = u >> 4, c = u & 15;
            size_t g = (size_t)r * QSTR + c * 8;
            uint32_t s = swz256(r, c);
            *(uint4*)(smem + SQ_HI + s) = *(const uint4*)(qh + g);
            *(uint4*)(smem + SQ_LO + s) = *(const uint4*)(ql + g);
        }
    }

    float m0 = -INFINITY, m1 = -INFINITY, l0 = 0.0f, l1 = 0.0f;
    float oacc[16][4];
#pragma unroll
    for (int i = 0; i < 16; i++)
#pragma unroll
        for (int j = 0; j < 4; j++) oacc[i][j] = 0.0f;

    const int row_lo = qb * 128 + warp_m + (lane >> 2);   // thread row 0
    const int nkb = 2 * qb + 2;

    for (int kb = 0; kb < nkb; kb++) {
        __syncthreads();
        {
            const __nv_bfloat16* kh = khi + ((size_t)(b * SS + kb * 64)) * KSTR + kvh * HD;
            const __nv_bfloat16* kl = klo + ((size_t)(b * SS + kb * 64)) * KSTR + kvh * HD;
            const __nv_bfloat16* vh = vhi + ((size_t)(b * SS + kb * 64)) * KSTR + kvh * HD;
            const __nv_bfloat16* vl = vlo + ((size_t)(b * SS + kb * 64)) * KSTR + kvh * HD;
#pragma unroll
            for (int i = 0; i < 4; i++) {
                int u = t + i * 256;
                int r = u >> 4, c = u & 15;
                size_t g = (size_t)r * KSTR + c * 8;
                uint32_t s = swz256(r, c);
                *(uint4*)(smem + SK_HI + s) = *(const uint4*)(kh + g);
                *(uint4*)(smem + SK_LO + s) = *(const uint4*)(kl + g);
                *(uint4*)(smem + SV_HI + s) = *(const uint4*)(vh + g);
                *(uint4*)(smem + SV_LO + s) = *(const uint4*)(vl + g);
            }
        }
        __syncthreads();

        // warp tile fully masked? (all cols > all rows)
        if (kb * 64 > qb * 128 + warp_m + 15) continue;
        const bool need_mask = (kb * 64 + 63 > qb * 128 + warp_m);

        // ---- S = Q K^T (pre-scaled Q) ----
        float sacc[8][4];
#pragma unroll
        for (int i = 0; i < 8; i++)
#pragma unroll
            for (int j = 0; j < 4; j++) sacc[i][j] = 0.0f;

#pragma unroll
        for (int ks = 0; ks < 8; ks++) {
            uint32_t ah[4], al[4];
            {
                int ar = warp_m + (lane & 15);
                int ac = ks * 2 + (lane >> 4);
                uint32_t off = swz256(ar, ac);
                ldsm_x4(ah, sb + SQ_HI + off);
                ldsm_x4(al, sb + SQ_LO + off);
            }
#pragma unroll
            for (int np = 0; np < 4; np++) {
                uint32_t bh[4], bl[4];
                int br = np * 16 + (lane & 7) + ((lane >> 4) & 1) * 8;
                int bc = ks * 2 + ((lane >> 3) & 1);
                uint32_t off = swz256(br, bc);
                ldsm_x4(bh, sb + SK_HI + off);
                ldsm_x4(bl, sb + SK_LO + off);
#pragma unroll
                for (int half = 0; half < 2; half++) {
                    int nt = np * 2 + half, pb = half * 2;
                    mma16816(sacc[nt], ah, bh[pb], bh[pb + 1]);
                    mma16816(sacc[nt], ah, bl[pb], bl[pb + 1]);
                    mma16816(sacc[nt], al, bh[pb], bh[pb + 1]);
                }
            }
        }

        // ---- mask + online softmax (registers) ----
        if (need_mask) {
#pragma unroll
            for (int nt = 0; nt < 8; nt++) {
                int col = kb * 64 + nt * 8 + (lane & 3) * 2;
#pragma unroll
                for (int j = 0; j < 4; j++) {
                    int cc = col + (j & 1);
                    int rr = row_lo + ((j >> 1) << 3);
                    if (cc > rr) sacc[nt][j] = -INFINITY;
                }
            }
        }

        float mt0 = -INFINITY, mt1 = -INFINITY;
#pragma unroll
        for (int nt = 0; nt < 8; nt++) {
            mt0 = fmaxf(mt0, fmaxf(sacc[nt][0], sacc[nt][1]));
            mt1 = fmaxf(mt1, fmaxf(sacc[nt][2], sacc[nt][3]));
        }
        mt0 = fmaxf(mt0, __shfl_xor_sync(0xffffffffu, mt0, 1));
        mt0 = fmaxf(mt0, __shfl_xor_sync(0xffffffffu, mt0, 2));
        mt1 = fmaxf(mt1, __shfl_xor_sync(0xffffffffu, mt1, 1));
        mt1 = fmaxf(mt1, __shfl_xor_sync(0xffffffffu, mt1, 2));

        float mn0 = fmaxf(m0, mt0), mn1 = fmaxf(m1, mt1);
        float sc0 = __expf(m0 - mn0), sc1 = __expf(m1 - mn1);
        m0 = mn0; m1 = mn1;

        float ps0 = 0.0f, ps1 = 0.0f;
#pragma unroll
        for (int nt = 0; nt < 8; nt++) {
            sacc[nt][0] = __expf(sacc[nt][0] - mn0);
            sacc[nt][1] = __expf(sacc[nt][1] - mn0);
            sacc[nt][2] = __expf(sacc[nt][2] - mn1);
            sacc[nt][3] = __expf(sacc[nt][3] - mn1);
            ps0 += sacc[nt][0] + sacc[nt][1];
            ps1 += sacc[nt][2] + sacc[nt][3];
        }
        ps0 += __shfl_xor_sync(0xffffffffu, ps0, 1);
        ps0 += __shfl_xor_sync(0xffffffffu, ps0, 2);
        ps1 += __shfl_xor_sync(0xffffffffu, ps1, 1);
        ps1 += __shfl_xor_sync(0xffffffffu, ps1, 2);
        l0 = l0 * sc0 + ps0;
        l1 = l1 * sc1 + ps1;

#pragma unroll
        for (int nt = 0; nt < 16; nt++) {
            oacc[nt][0] *= sc0; oacc[nt][1] *= sc0;
            oacc[nt][2] *= sc1; oacc[nt][3] *= sc1;
        }

        // ---- O += P V ----
#pragma unroll
        for (int ks = 0; ks < 4; ks++) {
            uint32_t phi[4], plo[4];
            split2(sacc[2 * ks][0], sacc[2 * ks][1], phi[0], plo[0]);
            split2(sacc[2 * ks][2], sacc[2 * ks][3], phi[1], plo[1]);
            split2(sacc[2 * ks + 1][0], sacc[2 * ks + 1][1], phi[2], plo[2]);
            split2(sacc[2 * ks + 1][2], sacc[2 * ks + 1][3], phi[3], plo[3]);
#pragma unroll
            for (int dp = 0; dp < 8; dp++) {
                uint32_t vh4[4], vl4[4];
                int vr = ks * 16 + (lane & 7) + ((lane >> 3) & 1) * 8;
                int vc = dp * 2 + (lane >> 4);
                uint32_t off = swz256(vr, vc);
                ldsm_x4_t(vh4, sb + SV_HI + off);
                ldsm_x4_t(vl4, sb + SV_LO + off);
                mma16816(oacc[dp * 2], phi, vh4[0], vh4[1]);
                mma16816(oacc[dp * 2], phi, vl4[0], vl4[1]);
                mma16816(oacc[dp * 2], plo, vh4[0], vh4[1]);
                mma16816(oacc[dp * 2 + 1], phi, vh4[2], vh4[3]);
                mma16816(oacc[dp * 2 + 1], phi, vl4[2], vl4[3]);
                mma16816(oacc[dp * 2 + 1], plo, vh4[2], vh4[3]);
            }
        }
    }

    // ---- epilogue ----
    float il0 = 1.0f / l0, il1 = 1.0f / l1;
    float* ob = o + ((size_t)(b * SS)) * QSTR + h * HD;
    int r0 = qb * 128 + warp_m + (lane >> 2);
#pragma unroll
    for (int nt = 0; nt < 16; nt++) {
        int dim = nt * 8 + (lane & 3) * 2;
        float2 v0 = make_float2(oacc[nt][0] * il0, oacc[nt][1] * il0);
        float2 v1 = make_float2(oacc[nt][2] * il1, oacc[nt][3] * il1);
        *(float2*)&ob[(size_t)r0 * QSTR + dim] = v0;
        *(float2*)&ob[(size_t)(r0 + 8) * QSTR + dim] = v1;
    }
}

// ---------------------------------------------------------------------------
extern "C" void kernel_launch(void* const* d_in, const int* in_sizes, int n_in,
                              void* d_out, int out_size)
{
    const float* hs  = (const float*)d_in[0];
    const float* q_w = (const float*)d_in[1];
    const float* k_w = (const float*)d_in[2];
    const float* v_w = (const float*)d_in[3];
    const float* o_w = (const float*)d_in[4];
    const float* qn  = (const float*)d_in[5];
    const float* kn  = (const float*)d_in[6];
    float* out = (float*)d_out;

    float *pq, *pk, *pv, *pa;
    __nv_bfloat16 *pqh, *pql, *pkh, *pkl, *pvh, *pvl;
    cudaGetSymbolAddress((void**)&pq, g_q);
    cudaGetSymbolAddress((void**)&pk, g_k);
    cudaGetSymbolAddress((void**)&pv, g_v);
    cudaGetSymbolAddress((void**)&pa, g_attn);
    cudaGetSymbolAddress((void**)&pqh, g_qhi);
    cudaGetSymbolAddress((void**)&pql, g_qlo);
    cudaGetSymbolAddress((void**)&pkh, g_khi);
    cudaGetSymbolAddress((void**)&pkl, g_klo);
    cudaGetSymbolAddress((void**)&pvh, g_vhi);
    cudaGetSymbolAddress((void**)&pvl, g_vlo);

    const int M = BB * SS;     // 4096
    const int K = HH;          // 2048
    const float RSCALE = 0.08838834764831845f; // 1/sqrt(128)

    // QKV projections (split-bf16 mma.sync)
    gemm_tc<<<dim3((NH * HD) / 128, M / 128), 512>>>(hs, q_w, pq, M, NH * HD, K);
    gemm_tc<<<dim3((NKV * HD) / 128, M / 128), 512>>>(hs, k_w, pk, M, NKV * HD, K);
    gemm_tc<<<dim3((NKV * HD) / 128, M / 128), 512>>>(hs, v_w, pv, M, NKV * HD, K);

    // RMSNorm + RoPE -> bf16 hi/lo (Q pre-scaled by 1/sqrt(d))
    rmsnorm_rope<<<dim3(M, NH), 128>>>(pq, qn, pqh, pql, NH, RSCALE);
    rmsnorm_rope<<<dim3(M, NKV), 128>>>(pk, kn, pkh, pkl, NKV, 1.0f);
    v_convert<<<(M * NKV * HD) / 256, 256>>>(pv, pvh, pvl);

    // tensor-core causal flash attention (GQA)
    cudaFuncSetAttribute(flash_attn_tc, cudaFuncAttributeMaxDynamicSharedMemorySize,
                         FL_SMEM);
    flash_attn_tc<<<dim3(SS / 128, NH, BB), 256, FL_SMEM>>>(pqh, pql, pkh, pkl,
                                                            pvh, pvl, pa);

    // output projection
    gemm_tc<<<dim3(HH / 128, M / 128), 512>>>(pa, o_w, out, M, HH, K);
}

// round 6
// speedup vs baseline: 3.2512x; 1.3116x over previous
#include <cuda_runtime.h>
#include <cuda_bf16.h>
#include <stdint.h>
#include <math.h>

#define BB 2
#define SS 2048
#define HH 2048
#define NH 16
#define NKV 4
#define HD 128

// ---------------- scratch (device globals: allocation-free) ----------------
__device__ float g_q[(size_t)BB * SS * NH * HD];
__device__ float g_k[(size_t)BB * SS * NKV * HD];
__device__ float g_v[(size_t)BB * SS * NKV * HD];
// pre-split bf16 operands
__device__ __nv_bfloat16 g_hs_hi[(size_t)BB * SS * HH];
__device__ __nv_bfloat16 g_hs_lo[(size_t)BB * SS * HH];
__device__ __nv_bfloat16 g_qw_hi[(size_t)NH * HD * HH];
__device__ __nv_bfloat16 g_qw_lo[(size_t)NH * HD * HH];
__device__ __nv_bfloat16 g_kw_hi[(size_t)NKV * HD * HH];
__device__ __nv_bfloat16 g_kw_lo[(size_t)NKV * HD * HH];
__device__ __nv_bfloat16 g_vw_hi[(size_t)NKV * HD * HH];
__device__ __nv_bfloat16 g_vw_lo[(size_t)NKV * HD * HH];
__device__ __nv_bfloat16 g_ow_hi[(size_t)HH * NH * HD];
__device__ __nv_bfloat16 g_ow_lo[(size_t)HH * NH * HD];
// post-norm attention operands
__device__ __nv_bfloat16 g_qhi[(size_t)BB * SS * NH * HD];
__device__ __nv_bfloat16 g_qlo[(size_t)BB * SS * NH * HD];
__device__ __nv_bfloat16 g_khi[(size_t)BB * SS * NKV * HD];
__device__ __nv_bfloat16 g_klo[(size_t)BB * SS * NKV * HD];
__device__ __nv_bfloat16 g_vhi[(size_t)BB * SS * NKV * HD];
__device__ __nv_bfloat16 g_vlo[(size_t)BB * SS * NKV * HD];
// attention output (bf16 hi/lo, feeds O projection)
__device__ __nv_bfloat16 g_ahi[(size_t)BB * SS * NH * HD];
__device__ __nv_bfloat16 g_alo[(size_t)BB * SS * NH * HD];

// ===================== warp-MMA helpers =====================
__device__ __forceinline__ uint32_t smem_to_u32(const void* p) {
    uint32_t a;
    asm("{ .reg .u64 t; cvta.to.shared.u64 t, %1; cvt.u32.u64 %0, t; }"
        : "=r"(a) : "l"(p));
    return a;
}
__device__ __forceinline__ void ldsm_x4(uint32_t r[4], uint32_t addr) {
    asm volatile("ldmatrix.sync.aligned.m8n8.x4.shared.b16 {%0,%1,%2,%3}, [%4];"
                 : "=r"(r[0]), "=r"(r[1]), "=r"(r[2]), "=r"(r[3]) : "r"(addr));
}
__device__ __forceinline__ void ldsm_x4_t(uint32_t r[4], uint32_t addr) {
    asm volatile("ldmatrix.sync.aligned.m8n8.x4.trans.shared.b16 {%0,%1,%2,%3}, [%4];"
                 : "=r"(r[0]), "=r"(r[1]), "=r"(r[2]), "=r"(r[3]) : "r"(addr));
}
__device__ __forceinline__ void mma16816(float c[4], const uint32_t a[4],
                                         const uint32_t b0, const uint32_t b1) {
    asm volatile(
        "mma.sync.aligned.m16n8k16.row.col.f32.bf16.bf16.f32 "
        "{%0,%1,%2,%3}, {%4,%5,%6,%7}, {%8,%9}, {%0,%1,%2,%3};"
        : "+f"(c[0]), "+f"(c[1]), "+f"(c[2]), "+f"(c[3])
        : "r"(a[0]), "r"(a[1]), "r"(a[2]), "r"(a[3]), "r"(b0), "r"(b1));
}
__device__ __forceinline__ void cp_async16(uint32_t dst, const void* src) {
    asm volatile("cp.async.cg.shared.global [%0], [%1], 16;"
                 :: "r"(dst), "l"(src) : "memory");
}
#define CP_COMMIT() asm volatile("cp.async.commit_group;" ::: "memory")
#define CP_WAIT(n)  asm volatile("cp.async.wait_group %0;" :: "n"(n) : "memory")

__device__ __forceinline__ void split2(float x, float y, uint32_t& hi, uint32_t& lo) {
    __nv_bfloat16 hx = __float2bfloat16_rn(x);
    __nv_bfloat16 hy = __float2bfloat16_rn(y);
    __nv_bfloat16 lx = __float2bfloat16_rn(x - __bfloat162float(hx));
    __nv_bfloat16 ly = __float2bfloat16_rn(y - __bfloat162float(hy));
    hi = (uint32_t)__bfloat16_as_ushort(hx) | ((uint32_t)__bfloat16_as_ushort(hy) << 16);
    lo = (uint32_t)__bfloat16_as_ushort(lx) | ((uint32_t)__bfloat16_as_ushort(ly) << 16);
}

// swizzled byte offset in a [rows x 32 bf16] tile (64B rows, 4x16B units)
__device__ __forceinline__ uint32_t swz(int row, int c) {
    return (uint32_t)(row * 64 + ((c ^ ((row >> 1) & 3)) << 4));
}
// swizzled byte offset in a [rows x 128 bf16] tile (256B rows, 16x16B units)
__device__ __forceinline__ uint32_t swz256(int row, int c) {
    return (uint32_t)(row * 256 + ((c ^ (row & 7)) << 4));
}

// ---------------------------------------------------------------------------
// elementwise fp32 -> bf16 (hi, lo) split, float4 per thread
// ---------------------------------------------------------------------------
__global__ void split_f32(const float* __restrict__ x,
                          __nv_bfloat16* __restrict__ hi,
                          __nv_bfloat16* __restrict__ lo)
{
    size_t i = ((size_t)blockIdx.x * blockDim.x + threadIdx.x) * 4;
    float4 f = *(const float4*)(x + i);
    uint2 h, l;
    split2(f.x, f.y, h.x, l.x);
    split2(f.z, f.w, h.y, l.y);
    *(uint2*)(hi + i) = h;
    *(uint2*)(lo + i) = l;
}

// ---------------------------------------------------------------------------
// pure-bf16 split GEMM on mma.sync with 3-stage cp.async pipeline.
// C[M][N] = (Ahi+Alo)[M][K] * (Bhi+Blo)[N][K]^T  (fp32 out, 3 split passes)
// BM=BN=128, BK=32, 512 threads (16 warps 4x4), warp tile 32x32.
// ---------------------------------------------------------------------------
#define GS_AH 0
#define GS_AL 8192
#define GS_BH 16384
#define GS_BL 24576
#define GS_STAGE 32768
#define GS_SMEM (3 * GS_STAGE)

__global__ void __launch_bounds__(512) gemm_bf16(
    const __nv_bfloat16* __restrict__ Ahi, const __nv_bfloat16* __restrict__ Alo,
    const __nv_bfloat16* __restrict__ Bhi, const __nv_bfloat16* __restrict__ Blo,
    float* __restrict__ C, int M, int N, int K)
{
    extern __shared__ char smem[];
    const uint32_t sb = smem_to_u32(smem);

    const int t = threadIdx.x;
    const int lane = t & 31, wid = t >> 5;
    const int bm = blockIdx.y * 128, bn = blockIdx.x * 128;
    const int wm = (wid & 3) * 32;
    const int wn = (wid >> 2) * 32;

    // staging map: thread t -> (row = t>>2, 16B unit c = t&3)
    const int lrow = t >> 2, lc = t & 3;
    const size_t ga = (size_t)(bm + lrow) * K + lc * 8;
    const size_t gb = (size_t)(bn + lrow) * K + lc * 8;
    const uint32_t st = swz(lrow, lc);
    const int nch = K >> 5;

    auto issue = [&](int ch) {
        uint32_t base = sb + (uint32_t)(ch % 3) * GS_STAGE + st;
        size_t ka = ga + (size_t)ch * 32;
        size_t kb = gb + (size_t)ch * 32;
        cp_async16(base + GS_AH, Ahi + ka);
        cp_async16(base + GS_AL, Alo + ka);
        cp_async16(base + GS_BH, Bhi + kb);
        cp_async16(base + GS_BL, Blo + kb);
    };

    issue(0); CP_COMMIT();
    issue(1); CP_COMMIT();

    float acc[2][4][4];
#pragma unroll
    for (int i = 0; i < 2; i++)
#pragma unroll
        for (int j = 0; j < 4; j++)
#pragma unroll
            for (int q = 0; q < 4; q++) acc[i][j][q] = 0.0f;

    for (int ch = 0; ch < nch; ch++) {
        CP_WAIT(1);
        __syncthreads();
        if (ch + 2 < nch) issue(ch + 2);
        CP_COMMIT();

        const uint32_t base = sb + (uint32_t)(ch % 3) * GS_STAGE;
#pragma unroll
        for (int ks = 0; ks < 2; ks++) {
            uint32_t ah[2][4], al[2][4];
#pragma unroll
            for (int mt = 0; mt < 2; mt++) {
                int row = wm + mt * 16 + (lane & 15);
                int c = ks * 2 + (lane >> 4);
                uint32_t off = swz(row, c);
                ldsm_x4(ah[mt], base + GS_AH + off);
                ldsm_x4(al[mt], base + GS_AL + off);
            }
#pragma unroll
            for (int np = 0; np < 2; np++) {
                uint32_t bh[4], bl[4];
                int row = wn + np * 16 + (lane & 7) + ((lane >> 4) & 1) * 8;
                int c = ks * 2 + ((lane >> 3) & 1);
                uint32_t off = swz(row, c);
                ldsm_x4(bh, base + GS_BH + off);
                ldsm_x4(bl, base + GS_BL + off);
#pragma unroll
                for (int half = 0; half < 2; half++) {
                    int nt = np * 2 + half, pb = half * 2;
#pragma unroll
                    for (int mt = 0; mt < 2; mt++) {
                        mma16816(acc[mt][nt], ah[mt], bh[pb], bh[pb + 1]);
                        mma16816(acc[mt][nt], ah[mt], bl[pb], bl[pb + 1]);
                        mma16816(acc[mt][nt], al[mt], bh[pb], bh[pb + 1]);
                    }
                }
            }
        }
        __syncthreads();
    }

#pragma unroll
    for (int mt = 0; mt < 2; mt++)
#pragma unroll
        for (int nt = 0; nt < 4; nt++) {
            int r0 = bm + wm + mt * 16 + (lane >> 2);
            int c0 = bn + wn + nt * 8 + (lane & 3) * 2;
            float2 v0 = make_float2(acc[mt][nt][0], acc[mt][nt][1]);
            float2 v1 = make_float2(acc[mt][nt][2], acc[mt][nt][3]);
            *(float2*)&C[(size_t)r0 * N + c0] = v0;
            *(float2*)&C[(size_t)(r0 + 8) * N + c0] = v1;
        }
}

// ---------------------------------------------------------------------------
// Fused per-head RMSNorm + RoPE -> split bf16 hi/lo (optionally pre-scaled).
// ---------------------------------------------------------------------------
__global__ void rmsnorm_rope(const float* __restrict__ x, const float* __restrict__ w,
                             __nv_bfloat16* __restrict__ hi, __nv_bfloat16* __restrict__ lo,
                             int nheads, float prescale)
{
    const int row = blockIdx.x;
    const int h   = blockIdx.y;
    const int s   = row & (SS - 1);
    const int d   = threadIdx.x;

    const size_t base = ((size_t)row * nheads + h) * HD;
    float val = x[base + d];

    float ss = val * val;
#pragma unroll
    for (int off = 16; off > 0; off >>= 1)
        ss += __shfl_xor_sync(0xffffffffu, ss, off);

    __shared__ float red[4];
    __shared__ float xs[128];
    const int warp = d >> 5, lane = d & 31;
    if (lane == 0) red[warp] = ss;
    __syncthreads();
    float tot = red[0] + red[1] + red[2] + red[3];
    float xn  = val * rsqrtf(tot * (1.0f / 128.0f) + 1e-5f) * w[d];
    xs[d] = xn;
    __syncthreads();

    const int i = d & 63;
    float inv_freq = expf(-(float)i * (13.122363377404328f / 64.0f));
    float ang = (float)s * inv_freq;
    float sn, cs;
    sincosf(ang, &sn, &cs);

    float other = xs[d ^ 64];
    float res = (d < 64) ? (xn * cs - other * sn) : (xn * cs + other * sn);
    res *= prescale;

    __nv_bfloat16 hb = __float2bfloat16_rn(res);
    __nv_bfloat16 lb = __float2bfloat16_rn(res - __bfloat162float(hb));
    hi[base + d] = hb;
    lo[base + d] = lb;
}

// ---------------------------------------------------------------------------
// Tensor-core causal flash attention, split-bf16, GQA.
// BM=128, BN=64, D=128. 256 threads = 8 warps; warp tile m16 x n64.
// Epilogue writes bf16 hi/lo (feeds O projection).
// ---------------------------------------------------------------------------
#define SQ_HI 0
#define SQ_LO 32768
#define SK_HI 65536
#define SK_LO 81920
#define SV_HI 98304
#define SV_LO 114688
#define FL_SMEM 131072

__global__ void __launch_bounds__(256) flash_attn_tc(
    const __nv_bfloat16* __restrict__ qhi, const __nv_bfloat16* __restrict__ qlo,
    const __nv_bfloat16* __restrict__ khi, const __nv_bfloat16* __restrict__ klo,
    const __nv_bfloat16* __restrict__ vhi, const __nv_bfloat16* __restrict__ vlo,
    __nv_bfloat16* __restrict__ ohi, __nv_bfloat16* __restrict__ olo)
{
    extern __shared__ char smem[];
    const uint32_t sb = smem_to_u32(smem);
    const int t = threadIdx.x, lane = t & 31, wid = t >> 5;
    const int qb = blockIdx.x, h = blockIdx.y, b = blockIdx.z;
    const int kvh = h >> 2;
    const int warp_m = wid * 16;
    const int QSTR = NH * HD;
    const int KSTR = NKV * HD;

    {
        const __nv_bfloat16* qh = qhi + ((size_t)(b * SS + qb * 128)) * QSTR + h * HD;
        const __nv_bfloat16* ql = qlo + ((size_t)(b * SS + qb * 128)) * QSTR + h * HD;
#pragma unroll
        for (int i = 0; i < 8; i++) {
            int u = t + i * 256;
            int r = u >> 4, c = u & 15;
            size_t g = (size_t)r * QSTR + c * 8;
            uint32_t s = swz256(r, c);
            *(uint4*)(smem + SQ_HI + s) = *(const uint4*)(qh + g);
            *(uint4*)(smem + SQ_LO + s) = *(const uint4*)(ql + g);
        }
    }

    float m0 = -INFINITY, m1 = -INFINITY, l0 = 0.0f, l1 = 0.0f;
    float oacc[16][4];
#pragma unroll
    for (int i = 0; i < 16; i++)
#pragma unroll
        for (int j = 0; j < 4; j++) oacc[i][j] = 0.0f;

    const int row_lo = qb * 128 + warp_m + (lane >> 2);
    const int nkb = 2 * qb + 2;

    for (int kb = 0; kb < nkb; kb++) {
        __syncthreads();
        {
            const __nv_bfloat16* kh = khi + ((size_t)(b * SS + kb * 64)) * KSTR + kvh * HD;
            const __nv_bfloat16* kl = klo + ((size_t)(b * SS + kb * 64)) * KSTR + kvh * HD;
            const __nv_bfloat16* vh = vhi + ((size_t)(b * SS + kb * 64)) * KSTR + kvh * HD;
            const __nv_bfloat16* vl = vlo + ((size_t)(b * SS + kb * 64)) * KSTR + kvh * HD;
#pragma unroll
            for (int i = 0; i < 4; i++) {
                int u = t + i * 256;
                int r = u >> 4, c = u & 15;
                size_t g = (size_t)r * KSTR + c * 8;
                uint32_t s = swz256(r, c);
                *(uint4*)(smem + SK_HI + s) = *(const uint4*)(kh + g);
                *(uint4*)(smem + SK_LO + s) = *(const uint4*)(kl + g);
                *(uint4*)(smem + SV_HI + s) = *(const uint4*)(vh + g);
                *(uint4*)(smem + SV_LO + s) = *(const uint4*)(vl + g);
            }
        }
        __syncthreads();

        if (kb * 64 > qb * 128 + warp_m + 15) continue;
        const bool need_mask = (kb * 64 + 63 > qb * 128 + warp_m);

        float sacc[8][4];
#pragma unroll
        for (int i = 0; i < 8; i++)
#pragma unroll
            for (int j = 0; j < 4; j++) sacc[i][j] = 0.0f;

#pragma unroll
        for (int ks = 0; ks < 8; ks++) {
            uint32_t ah[4], al[4];
            {
                int ar = warp_m + (lane & 15);
                int ac = ks * 2 + (lane >> 4);
                uint32_t off = swz256(ar, ac);
                ldsm_x4(ah, sb + SQ_HI + off);
                ldsm_x4(al, sb + SQ_LO + off);
            }
#pragma unroll
            for (int np = 0; np < 4; np++) {
                uint32_t bh[4], bl[4];
                int br = np * 16 + (lane & 7) + ((lane >> 4) & 1) * 8;
                int bc = ks * 2 + ((lane >> 3) & 1);
                uint32_t off = swz256(br, bc);
                ldsm_x4(bh, sb + SK_HI + off);
                ldsm_x4(bl, sb + SK_LO + off);
#pragma unroll
                for (int half = 0; half < 2; half++) {
                    int nt = np * 2 + half, pb = half * 2;
                    mma16816(sacc[nt], ah, bh[pb], bh[pb + 1]);
                    mma16816(sacc[nt], ah, bl[pb], bl[pb + 1]);
                    mma16816(sacc[nt], al, bh[pb], bh[pb + 1]);
                }
            }
        }

        if (need_mask) {
#pragma unroll
            for (int nt = 0; nt < 8; nt++) {
                int col = kb * 64 + nt * 8 + (lane & 3) * 2;
#pragma unroll
                for (int j = 0; j < 4; j++) {
                    int cc = col + (j & 1);
                    int rr = row_lo + ((j >> 1) << 3);
                    if (cc > rr) sacc[nt][j] = -INFINITY;
                }
            }
        }

        float mt0 = -INFINITY, mt1 = -INFINITY;
#pragma unroll
        for (int nt = 0; nt < 8; nt++) {
            mt0 = fmaxf(mt0, fmaxf(sacc[nt][0], sacc[nt][1]));
            mt1 = fmaxf(mt1, fmaxf(sacc[nt][2], sacc[nt][3]));
        }
        mt0 = fmaxf(mt0, __shfl_xor_sync(0xffffffffu, mt0, 1));
        mt0 = fmaxf(mt0, __shfl_xor_sync(0xffffffffu, mt0, 2));
        mt1 = fmaxf(mt1, __shfl_xor_sync(0xffffffffu, mt1, 1));
        mt1 = fmaxf(mt1, __shfl_xor_sync(0xffffffffu, mt1, 2));

        float mn0 = fmaxf(m0, mt0), mn1 = fmaxf(m1, mt1);
        float sc0 = __expf(m0 - mn0), sc1 = __expf(m1 - mn1);
        m0 = mn0; m1 = mn1;

        float ps0 = 0.0f, ps1 = 0.0f;
#pragma unroll
        for (int nt = 0; nt < 8; nt++) {
            sacc[nt][0] = __expf(sacc[nt][0] - mn0);
            sacc[nt][1] = __expf(sacc[nt][1] - mn0);
            sacc[nt][2] = __expf(sacc[nt][2] - mn1);
            sacc[nt][3] = __expf(sacc[nt][3] - mn1);
            ps0 += sacc[nt][0] + sacc[nt][1];
            ps1 += sacc[nt][2] + sacc[nt][3];
        }
        ps0 += __shfl_xor_sync(0xffffffffu, ps0, 1);
        ps0 += __shfl_xor_sync(0xffffffffu, ps0, 2);
        ps1 += __shfl_xor_sync(0xffffffffu, ps1, 1);
        ps1 += __shfl_xor_sync(0xffffffffu, ps1, 2);
        l0 = l0 * sc0 + ps0;
        l1 = l1 * sc1 + ps1;

#pragma unroll
        for (int nt = 0; nt < 16; nt++) {
            oacc[nt][0] *= sc0; oacc[nt][1] *= sc0;
            oacc[nt][2] *= sc1; oacc[nt][3] *= sc1;
        }

#pragma unroll
        for (int ks = 0; ks < 4; ks++) {
            uint32_t phi[4], plo[4];
            split2(sacc[2 * ks][0], sacc[2 * ks][1], phi[0], plo[0]);
            split2(sacc[2 * ks][2], sacc[2 * ks][3], phi[1], plo[1]);
            split2(sacc[2 * ks + 1][0], sacc[2 * ks + 1][1], phi[2], plo[2]);
            split2(sacc[2 * ks + 1][2], sacc[2 * ks + 1][3], phi[3], plo[3]);
#pragma unroll
            for (int dp = 0; dp < 8; dp++) {
                uint32_t vh4[4], vl4[4];
                int vr = ks * 16 + (lane & 7) + ((lane >> 3) & 1) * 8;
                int vc = dp * 2 + (lane >> 4);
                uint32_t off = swz256(vr, vc);
                ldsm_x4_t(vh4, sb + SV_HI + off);
                ldsm_x4_t(vl4, sb + SV_LO + off);
                mma16816(oacc[dp * 2], phi, vh4[0], vh4[1]);
                mma16816(oacc[dp * 2], phi, vl4[0], vl4[1]);
                mma16816(oacc[dp * 2], plo, vh4[0], vh4[1]);
                mma16816(oacc[dp * 2 + 1], phi, vh4[2], vh4[3]);
                mma16816(oacc[dp * 2 + 1], phi, vl4[2], vl4[3]);
                mma16816(oacc[dp * 2 + 1], plo, vh4[2], vh4[3]);
            }
        }
    }

    // ---- epilogue: write bf16 hi/lo ----
    float il0 = 1.0f / l0, il1 = 1.0f / l1;
    __nv_bfloat16* oh = ohi + ((size_t)(b * SS)) * QSTR + h * HD;
    __nv_bfloat16* ol = olo + ((size_t)(b * SS)) * QSTR + h * HD;
    int r0 = qb * 128 + warp_m + (lane >> 2);
#pragma unroll
    for (int nt = 0; nt < 16; nt++) {
        int dim = nt * 8 + (lane & 3) * 2;
        uint32_t h0, l0b, h1, l1b;
        split2(oacc[nt][0] * il0, oacc[nt][1] * il0, h0, l0b);
        split2(oacc[nt][2] * il1, oacc[nt][3] * il1, h1, l1b);
        *(uint32_t*)&oh[(size_t)r0 * QSTR + dim] = h0;
        *(uint32_t*)&ol[(size_t)r0 * QSTR + dim] = l0b;
        *(uint32_t*)&oh[(size_t)(r0 + 8) * QSTR + dim] = h1;
        *(uint32_t*)&ol[(size_t)(r0 + 8) * QSTR + dim] = l1b;
    }
}

// ---------------------------------------------------------------------------
extern "C" void kernel_launch(void* const* d_in, const int* in_sizes, int n_in,
                              void* d_out, int out_size)
{
    const float* hs  = (const float*)d_in[0];
    const float* q_w = (const float*)d_in[1];
    const float* k_w = (const float*)d_in[2];
    const float* v_w = (const float*)d_in[3];
    const float* o_w = (const float*)d_in[4];
    const float* qn  = (const float*)d_in[5];
    const float* kn  = (const float*)d_in[6];
    float* out = (float*)d_out;

    float *pq, *pk, *pv;
    __nv_bfloat16 *hsh, *hsl, *qwh, *qwl, *kwh, *kwl, *vwh, *vwl, *owh, *owl;
    __nv_bfloat16 *pqh, *pql, *pkh, *pkl, *pvh, *pvl, *pah, *pal;
    cudaGetSymbolAddress((void**)&pq, g_q);
    cudaGetSymbolAddress((void**)&pk, g_k);
    cudaGetSymbolAddress((void**)&pv, g_v);
    cudaGetSymbolAddress((void**)&hsh, g_hs_hi);
    cudaGetSymbolAddress((void**)&hsl, g_hs_lo);
    cudaGetSymbolAddress((void**)&qwh, g_qw_hi);
    cudaGetSymbolAddress((void**)&qwl, g_qw_lo);
    cudaGetSymbolAddress((void**)&kwh, g_kw_hi);
    cudaGetSymbolAddress((void**)&kwl, g_kw_lo);
    cudaGetSymbolAddress((void**)&vwh, g_vw_hi);
    cudaGetSymbolAddress((void**)&vwl, g_vw_lo);
    cudaGetSymbolAddress((void**)&owh, g_ow_hi);
    cudaGetSymbolAddress((void**)&owl, g_ow_lo);
    cudaGetSymbolAddress((void**)&pqh, g_qhi);
    cudaGetSymbolAddress((void**)&pql, g_qlo);
    cudaGetSymbolAddress((void**)&pkh, g_khi);
    cudaGetSymbolAddress((void**)&pkl, g_klo);
    cudaGetSymbolAddress((void**)&pvh, g_vhi);
    cudaGetSymbolAddress((void**)&pvl, g_vlo);
    cudaGetSymbolAddress((void**)&pah, g_ahi);
    cudaGetSymbolAddress((void**)&pal, g_alo);

    const int M = BB * SS;     // 4096
    const int K = HH;          // 2048
    const float RSCALE = 0.08838834764831845f;

    // pre-split operands to bf16 hi/lo
    split_f32<<<(M * HH) / 1024, 256>>>(hs, hsh, hsl);
    split_f32<<<(NH * HD * HH) / 1024, 256>>>(q_w, qwh, qwl);
    split_f32<<<(NKV * HD * HH) / 1024, 256>>>(k_w, kwh, kwl);
    split_f32<<<(NKV * HD * HH) / 1024, 256>>>(v_w, vwh, vwl);
    split_f32<<<(HH * NH * HD) / 1024, 256>>>(o_w, owh, owl);

    cudaFuncSetAttribute(gemm_bf16, cudaFuncAttributeMaxDynamicSharedMemorySize,
                         GS_SMEM);

    // QKV projections
    gemm_bf16<<<dim3((NH * HD) / 128, M / 128), 512, GS_SMEM>>>(hsh, hsl, qwh, qwl,
                                                                pq, M, NH * HD, K);
    gemm_bf16<<<dim3((NKV * HD) / 128, M / 128), 512, GS_SMEM>>>(hsh, hsl, kwh, kwl,
                                                                 pk, M, NKV * HD, K);
    gemm_bf16<<<dim3((NKV * HD) / 128, M / 128), 512, GS_SMEM>>>(hsh, hsl, vwh, vwl,
                                                                 pv, M, NKV * HD, K);

    // RMSNorm + RoPE -> bf16 hi/lo (Q pre-scaled); V split
    rmsnorm_rope<<<dim3(M, NH), 128>>>(pq, qn, pqh, pql, NH, RSCALE);
    rmsnorm_rope<<<dim3(M, NKV), 128>>>(pk, kn, pkh, pkl, NKV, 1.0f);
    split_f32<<<(M * NKV * HD) / 1024, 256>>>(pv, pvh, pvl);

    // tensor-core causal flash attention (GQA), writes bf16 hi/lo
    cudaFuncSetAttribute(flash_attn_tc, cudaFuncAttributeMaxDynamicSharedMemorySize,
                         FL_SMEM);
    flash_attn_tc<<<dim3(SS / 128, NH, BB), 256, FL_SMEM>>>(pqh, pql, pkh, pkl,
                                                            pvh, pvl, pah, pal);

    // output projection
    gemm_bf16<<<dim3(HH / 128, M / 128), 512, GS_SMEM>>>(pah, pal, owh, owl,
                                                         out, M, HH, K);
}

// round 7
// speedup vs baseline: 3.3921x; 1.0433x over previous
#include <cuda_runtime.h>
#include <cuda_bf16.h>
#include <stdint.h>
#include <math.h>

#define BB 2
#define SS 2048
#define HH 2048
#define NH 16
#define NKV 4
#define HD 128

// ---------------- scratch (device globals: allocation-free) ----------------
__device__ float g_q[(size_t)BB * SS * NH * HD];
__device__ float g_k[(size_t)BB * SS * NKV * HD];
__device__ float g_v[(size_t)BB * SS * NKV * HD];
// pre-split bf16 operands
__device__ __nv_bfloat16 g_hs_hi[(size_t)BB * SS * HH];
__device__ __nv_bfloat16 g_hs_lo[(size_t)BB * SS * HH];
__device__ __nv_bfloat16 g_qw_hi[(size_t)NH * HD * HH];
__device__ __nv_bfloat16 g_qw_lo[(size_t)NH * HD * HH];
__device__ __nv_bfloat16 g_kw_hi[(size_t)NKV * HD * HH];
__device__ __nv_bfloat16 g_kw_lo[(size_t)NKV * HD * HH];
__device__ __nv_bfloat16 g_vw_hi[(size_t)NKV * HD * HH];
__device__ __nv_bfloat16 g_vw_lo[(size_t)NKV * HD * HH];
__device__ __nv_bfloat16 g_ow_hi[(size_t)HH * NH * HD];
__device__ __nv_bfloat16 g_ow_lo[(size_t)HH * NH * HD];
// post-norm attention operands
__device__ __nv_bfloat16 g_qhi[(size_t)BB * SS * NH * HD];
__device__ __nv_bfloat16 g_qlo[(size_t)BB * SS * NH * HD];
__device__ __nv_bfloat16 g_khi[(size_t)BB * SS * NKV * HD];
__device__ __nv_bfloat16 g_klo[(size_t)BB * SS * NKV * HD];
__device__ __nv_bfloat16 g_vhi[(size_t)BB * SS * NKV * HD];
__device__ __nv_bfloat16 g_vlo[(size_t)BB * SS * NKV * HD];
// attention output (bf16 hi/lo, feeds O projection)
__device__ __nv_bfloat16 g_ahi[(size_t)BB * SS * NH * HD];
__device__ __nv_bfloat16 g_alo[(size_t)BB * SS * NH * HD];

// ===================== warp-MMA helpers =====================
__device__ __forceinline__ uint32_t smem_to_u32(const void* p) {
    uint32_t a;
    asm("{ .reg .u64 t; cvta.to.shared.u64 t, %1; cvt.u32.u64 %0, t; }"
        : "=r"(a) : "l"(p));
    return a;
}
__device__ __forceinline__ void ldsm_x4(uint32_t r[4], uint32_t addr) {
    asm volatile("ldmatrix.sync.aligned.m8n8.x4.shared.b16 {%0,%1,%2,%3}, [%4];"
                 : "=r"(r[0]), "=r"(r[1]), "=r"(r[2]), "=r"(r[3]) : "r"(addr));
}
__device__ __forceinline__ void ldsm_x4_t(uint32_t r[4], uint32_t addr) {
    asm volatile("ldmatrix.sync.aligned.m8n8.x4.trans.shared.b16 {%0,%1,%2,%3}, [%4];"
                 : "=r"(r[0]), "=r"(r[1]), "=r"(r[2]), "=r"(r[3]) : "r"(addr));
}
__device__ __forceinline__ void mma16816(float c[4], const uint32_t a[4],
                                         const uint32_t b0, const uint32_t b1) {
    asm volatile(
        "mma.sync.aligned.m16n8k16.row.col.f32.bf16.bf16.f32 "
        "{%0,%1,%2,%3}, {%4,%5,%6,%7}, {%8,%9}, {%0,%1,%2,%3};"
        : "+f"(c[0]), "+f"(c[1]), "+f"(c[2]), "+f"(c[3])
        : "r"(a[0]), "r"(a[1]), "r"(a[2]), "r"(a[3]), "r"(b0), "r"(b1));
}
__device__ __forceinline__ void cp_async16(uint32_t dst, const void* src) {
    asm volatile("cp.async.cg.shared.global [%0], [%1], 16;"
                 :: "r"(dst), "l"(src) : "memory");
}
#define CP_COMMIT() asm volatile("cp.async.commit_group;" ::: "memory")
#define CP_WAIT(n)  asm volatile("cp.async.wait_group %0;" :: "n"(n) : "memory")

__device__ __forceinline__ void split2(float x, float y, uint32_t& hi, uint32_t& lo) {
    __nv_bfloat16 hx = __float2bfloat16_rn(x);
    __nv_bfloat16 hy = __float2bfloat16_rn(y);
    __nv_bfloat16 lx = __float2bfloat16_rn(x - __bfloat162float(hx));
    __nv_bfloat16 ly = __float2bfloat16_rn(y - __bfloat162float(hy));
    hi = (uint32_t)__bfloat16_as_ushort(hx) | ((uint32_t)__bfloat16_as_ushort(hy) << 16);
    lo = (uint32_t)__bfloat16_as_ushort(lx) | ((uint32_t)__bfloat16_as_ushort(ly) << 16);
}

// swizzled byte offset in a [rows x 32 bf16] tile (64B rows, 4x16B units)
__device__ __forceinline__ uint32_t swz(int row, int c) {
    return (uint32_t)(row * 64 + ((c ^ ((row >> 1) & 3)) << 4));
}
// swizzled byte offset in a [rows x 128 bf16] tile (256B rows, 16x16B units)
__device__ __forceinline__ uint32_t swz256(int row, int c) {
    return (uint32_t)(row * 256 + ((c ^ (row & 7)) << 4));
}

// ---------------------------------------------------------------------------
// elementwise fp32 -> bf16 (hi, lo) split, float4 per thread
// ---------------------------------------------------------------------------
__global__ void split_f32(const float* __restrict__ x,
                          __nv_bfloat16* __restrict__ hi,
                          __nv_bfloat16* __restrict__ lo)
{
    size_t i = ((size_t)blockIdx.x * blockDim.x + threadIdx.x) * 4;
    float4 f = *(const float4*)(x + i);
    uint2 h, l;
    split2(f.x, f.y, h.x, l.x);
    split2(f.z, f.w, h.y, l.y);
    *(uint2*)(hi + i) = h;
    *(uint2*)(lo + i) = l;
}

// ---------------------------------------------------------------------------
// pure-bf16 split GEMM on mma.sync with 3-stage cp.async pipeline.
// ---------------------------------------------------------------------------
#define GS_AH 0
#define GS_AL 8192
#define GS_BH 16384
#define GS_BL 24576
#define GS_STAGE 32768
#define GS_SMEM (3 * GS_STAGE)

__global__ void __launch_bounds__(512) gemm_bf16(
    const __nv_bfloat16* __restrict__ Ahi, const __nv_bfloat16* __restrict__ Alo,
    const __nv_bfloat16* __restrict__ Bhi, const __nv_bfloat16* __restrict__ Blo,
    float* __restrict__ C, int M, int N, int K)
{
    extern __shared__ char smem[];
    const uint32_t sb = smem_to_u32(smem);

    const int t = threadIdx.x;
    const int lane = t & 31, wid = t >> 5;
    const int bm = blockIdx.y * 128, bn = blockIdx.x * 128;
    const int wm = (wid & 3) * 32;
    const int wn = (wid >> 2) * 32;

    const int lrow = t >> 2, lc = t & 3;
    const size_t ga = (size_t)(bm + lrow) * K + lc * 8;
    const size_t gb = (size_t)(bn + lrow) * K + lc * 8;
    const uint32_t st = swz(lrow, lc);
    const int nch = K >> 5;

    auto issue = [&](int ch) {
        uint32_t base = sb + (uint32_t)(ch % 3) * GS_STAGE + st;
        size_t ka = ga + (size_t)ch * 32;
        size_t kb = gb + (size_t)ch * 32;
        cp_async16(base + GS_AH, Ahi + ka);
        cp_async16(base + GS_AL, Alo + ka);
        cp_async16(base + GS_BH, Bhi + kb);
        cp_async16(base + GS_BL, Blo + kb);
    };

    issue(0); CP_COMMIT();
    issue(1); CP_COMMIT();

    float acc[2][4][4];
#pragma unroll
    for (int i = 0; i < 2; i++)
#pragma unroll
        for (int j = 0; j < 4; j++)
#pragma unroll
            for (int q = 0; q < 4; q++) acc[i][j][q] = 0.0f;

    for (int ch = 0; ch < nch; ch++) {
        CP_WAIT(1);
        __syncthreads();
        if (ch + 2 < nch) issue(ch + 2);
        CP_COMMIT();

        const uint32_t base = sb + (uint32_t)(ch % 3) * GS_STAGE;
#pragma unroll
        for (int ks = 0; ks < 2; ks++) {
            uint32_t ah[2][4], al[2][4];
#pragma unroll
            for (int mt = 0; mt < 2; mt++) {
                int row = wm + mt * 16 + (lane & 15);
                int c = ks * 2 + (lane >> 4);
                uint32_t off = swz(row, c);
                ldsm_x4(ah[mt], base + GS_AH + off);
                ldsm_x4(al[mt], base + GS_AL + off);
            }
#pragma unroll
            for (int np = 0; np < 2; np++) {
                uint32_t bh[4], bl[4];
                int row = wn + np * 16 + (lane & 7) + ((lane >> 4) & 1) * 8;
                int c = ks * 2 + ((lane >> 3) & 1);
                uint32_t off = swz(row, c);
                ldsm_x4(bh, base + GS_BH + off);
                ldsm_x4(bl, base + GS_BL + off);
#pragma unroll
                for (int half = 0; half < 2; half++) {
                    int nt = np * 2 + half, pb = half * 2;
#pragma unroll
                    for (int mt = 0; mt < 2; mt++) {
                        mma16816(acc[mt][nt], ah[mt], bh[pb], bh[pb + 1]);
                        mma16816(acc[mt][nt], ah[mt], bl[pb], bl[pb + 1]);
                        mma16816(acc[mt][nt], al[mt], bh[pb], bh[pb + 1]);
                    }
                }
            }
        }
        __syncthreads();
    }

#pragma unroll
    for (int mt = 0; mt < 2; mt++)
#pragma unroll
        for (int nt = 0; nt < 4; nt++) {
            int r0 = bm + wm + mt * 16 + (lane >> 2);
            int c0 = bn + wn + nt * 8 + (lane & 3) * 2;
            float2 v0 = make_float2(acc[mt][nt][0], acc[mt][nt][1]);
            float2 v1 = make_float2(acc[mt][nt][2], acc[mt][nt][3]);
            *(float2*)&C[(size_t)r0 * N + c0] = v0;
            *(float2*)&C[(size_t)(r0 + 8) * N + c0] = v1;
        }
}

// ---------------------------------------------------------------------------
// Fused per-head RMSNorm + RoPE -> split bf16 hi/lo (optionally pre-scaled).
// ---------------------------------------------------------------------------
__global__ void rmsnorm_rope(const float* __restrict__ x, const float* __restrict__ w,
                             __nv_bfloat16* __restrict__ hi, __nv_bfloat16* __restrict__ lo,
                             int nheads, float prescale)
{
    const int row = blockIdx.x;
    const int h   = blockIdx.y;
    const int s   = row & (SS - 1);
    const int d   = threadIdx.x;

    const size_t base = ((size_t)row * nheads + h) * HD;
    float val = x[base + d];

    float ss = val * val;
#pragma unroll
    for (int off = 16; off > 0; off >>= 1)
        ss += __shfl_xor_sync(0xffffffffu, ss, off);

    __shared__ float red[4];
    __shared__ float xs[128];
    const int warp = d >> 5, lane = d & 31;
    if (lane == 0) red[warp] = ss;
    __syncthreads();
    float tot = red[0] + red[1] + red[2] + red[3];
    float xn  = val * rsqrtf(tot * (1.0f / 128.0f) + 1e-5f) * w[d];
    xs[d] = xn;
    __syncthreads();

    const int i = d & 63;
    float inv_freq = expf(-(float)i * (13.122363377404328f / 64.0f));
    float ang = (float)s * inv_freq;
    float sn, cs;
    sincosf(ang, &sn, &cs);

    float other = xs[d ^ 64];
    float res = (d < 64) ? (xn * cs - other * sn) : (xn * cs + other * sn);
    res *= prescale;

    __nv_bfloat16 hb = __float2bfloat16_rn(res);
    __nv_bfloat16 lb = __float2bfloat16_rn(res - __bfloat162float(hb));
    hi[base + d] = hb;
    lo[base + d] = lb;
}

// ---------------------------------------------------------------------------
// Tensor-core causal flash attention, split-bf16, GQA.
// BM=128, BN=64, D=128. 256 threads = 8 warps; warp tile m16 x n64.
// K/V double-buffered via cp.async. qb reversed for wave balance.
// ---------------------------------------------------------------------------
#define SQ_HI 0
#define SQ_LO 32768
#define KV_BASE 65536
#define KV_STAGE 65536
#define ST_KH 0
#define ST_KL 16384
#define ST_VH 32768
#define ST_VL 49152
#define FL_SMEM (KV_BASE + 2 * KV_STAGE)

__global__ void __launch_bounds__(256) flash_attn_tc(
    const __nv_bfloat16* __restrict__ qhi, const __nv_bfloat16* __restrict__ qlo,
    const __nv_bfloat16* __restrict__ khi, const __nv_bfloat16* __restrict__ klo,
    const __nv_bfloat16* __restrict__ vhi, const __nv_bfloat16* __restrict__ vlo,
    __nv_bfloat16* __restrict__ ohi, __nv_bfloat16* __restrict__ olo)
{
    extern __shared__ char smem[];
    const uint32_t sb = smem_to_u32(smem);
    const int t = threadIdx.x, lane = t & 31, wid = t >> 5;
    const int qb = gridDim.x - 1 - blockIdx.x;   // heavy blocks first
    const int h = blockIdx.y, b = blockIdx.z;
    const int kvh = h >> 2;
    const int warp_m = wid * 16;
    const int QSTR = NH * HD;
    const int KSTR = NKV * HD;

    // per-thread cp.async map for one KV stage: 4 rows-groups x 16B units
    const int cr = t >> 4, cc = t & 15;          // row 0..15(+16i), unit col
    const __nv_bfloat16* kh0 = khi + ((size_t)(b * SS)) * KSTR + kvh * HD;
    const __nv_bfloat16* kl0 = klo + ((size_t)(b * SS)) * KSTR + kvh * HD;
    const __nv_bfloat16* vh0 = vhi + ((size_t)(b * SS)) * KSTR + kvh * HD;
    const __nv_bfloat16* vl0 = vlo + ((size_t)(b * SS)) * KSTR + kvh * HD;

    auto issue_kv = [&](int kb) {
        uint32_t stage = sb + KV_BASE + (uint32_t)(kb & 1) * KV_STAGE;
#pragma unroll
        for (int i = 0; i < 4; i++) {
            int r = cr + i * 16;
            size_t g = (size_t)(kb * 64 + r) * KSTR + cc * 8;
            uint32_t s = swz256(r, cc);
            cp_async16(stage + ST_KH + s, kh0 + g);
            cp_async16(stage + ST_KL + s, kl0 + g);
            cp_async16(stage + ST_VH + s, vh0 + g);
            cp_async16(stage + ST_VL + s, vl0 + g);
        }
    };

    issue_kv(0); CP_COMMIT();

    // ---- load Q tile (128 x 128, hi+lo) ----
    {
        const __nv_bfloat16* qh = qhi + ((size_t)(b * SS + qb * 128)) * QSTR + h * HD;
        const __nv_bfloat16* ql = qlo + ((size_t)(b * SS + qb * 128)) * QSTR + h * HD;
#pragma unroll
        for (int i = 0; i < 8; i++) {
            int u = t + i * 256;
            int r = u >> 4, c = u & 15;
            size_t g = (size_t)r * QSTR + c * 8;
            uint32_t s = swz256(r, c);
            *(uint4*)(smem + SQ_HI + s) = *(const uint4*)(qh + g);
            *(uint4*)(smem + SQ_LO + s) = *(const uint4*)(ql + g);
        }
    }

    float m0 = -INFINITY, m1 = -INFINITY, l0 = 0.0f, l1 = 0.0f;
    float oacc[16][4];
#pragma unroll
    for (int i = 0; i < 16; i++)
#pragma unroll
        for (int j = 0; j < 4; j++) oacc[i][j] = 0.0f;

    const int row_lo = qb * 128 + warp_m + (lane >> 2);
    const int nkb = 2 * qb + 2;

    for (int kb = 0; kb < nkb; kb++) {
        __syncthreads();                 // stage (kb+1)&1 free for reuse
        if (kb + 1 < nkb) {
            issue_kv(kb + 1); CP_COMMIT();
            CP_WAIT(1);
        } else {
            CP_WAIT(0);
        }
        __syncthreads();                 // stage kb&1 visible to all

        if (kb * 64 > qb * 128 + warp_m + 15) continue;
        const bool need_mask = (kb * 64 + 63 > qb * 128 + warp_m);
        const uint32_t stage = sb + KV_BASE + (uint32_t)(kb & 1) * KV_STAGE;

        float sacc[8][4];
#pragma unroll
        for (int i = 0; i < 8; i++)
#pragma unroll
            for (int j = 0; j < 4; j++) sacc[i][j] = 0.0f;

#pragma unroll
        for (int ks = 0; ks < 8; ks++) {
            uint32_t ah[4], al[4];
            {
                int ar = warp_m + (lane & 15);
                int ac = ks * 2 + (lane >> 4);
                uint32_t off = swz256(ar, ac);
                ldsm_x4(ah, sb + SQ_HI + off);
                ldsm_x4(al, sb + SQ_LO + off);
            }
#pragma unroll
            for (int np = 0; np < 4; np++) {
                uint32_t bh[4], bl[4];
                int br = np * 16 + (lane & 7) + ((lane >> 4) & 1) * 8;
                int bc = ks * 2 + ((lane >> 3) & 1);
                uint32_t off = swz256(br, bc);
                ldsm_x4(bh, stage + ST_KH + off);
                ldsm_x4(bl, stage + ST_KL + off);
#pragma unroll
                for (int half = 0; half < 2; half++) {
                    int nt = np * 2 + half, pb = half * 2;
                    mma16816(sacc[nt], ah, bh[pb], bh[pb + 1]);
                    mma16816(sacc[nt], ah, bl[pb], bl[pb + 1]);
                    mma16816(sacc[nt], al, bh[pb], bh[pb + 1]);
                }
            }
        }

        if (need_mask) {
#pragma unroll
            for (int nt = 0; nt < 8; nt++) {
                int col = kb * 64 + nt * 8 + (lane & 3) * 2;
#pragma unroll
                for (int j = 0; j < 4; j++) {
                    int cc2 = col + (j & 1);
                    int rr = row_lo + ((j >> 1) << 3);
                    if (cc2 > rr) sacc[nt][j] = -INFINITY;
                }
            }
        }

        float mt0 = -INFINITY, mt1 = -INFINITY;
#pragma unroll
        for (int nt = 0; nt < 8; nt++) {
            mt0 = fmaxf(mt0, fmaxf(sacc[nt][0], sacc[nt][1]));
            mt1 = fmaxf(mt1, fmaxf(sacc[nt][2], sacc[nt][3]));
        }
        mt0 = fmaxf(mt0, __shfl_xor_sync(0xffffffffu, mt0, 1));
        mt0 = fmaxf(mt0, __shfl_xor_sync(0xffffffffu, mt0, 2));
        mt1 = fmaxf(mt1, __shfl_xor_sync(0xffffffffu, mt1, 1));
        mt1 = fmaxf(mt1, __shfl_xor_sync(0xffffffffu, mt1, 2));

        float mn0 = fmaxf(m0, mt0), mn1 = fmaxf(m1, mt1);
        float sc0 = __expf(m0 - mn0), sc1 = __expf(m1 - mn1);
        m0 = mn0; m1 = mn1;

        float ps0 = 0.0f, ps1 = 0.0f;
#pragma unroll
        for (int nt = 0; nt < 8; nt++) {
            sacc[nt][0] = __expf(sacc[nt][0] - mn0);
            sacc[nt][1] = __expf(sacc[nt][1] - mn0);
            sacc[nt][2] = __expf(sacc[nt][2] - mn1);
            sacc[nt][3] = __expf(sacc[nt][3] - mn1);
            ps0 += sacc[nt][0] + sacc[nt][1];
            ps1 += sacc[nt][2] + sacc[nt][3];
        }
        ps0 += __shfl_xor_sync(0xffffffffu, ps0, 1);
        ps0 += __shfl_xor_sync(0xffffffffu, ps0, 2);
        ps1 += __shfl_xor_sync(0xffffffffu, ps1, 1);
        ps1 += __shfl_xor_sync(0xffffffffu, ps1, 2);
        l0 = l0 * sc0 + ps0;
        l1 = l1 * sc1 + ps1;

#pragma unroll
        for (int nt = 0; nt < 16; nt++) {
            oacc[nt][0] *= sc0; oacc[nt][1] *= sc0;
            oacc[nt][2] *= sc1; oacc[nt][3] *= sc1;
        }

#pragma unroll
        for (int ks = 0; ks < 4; ks++) {
            uint32_t phi[4], plo[4];
            split2(sacc[2 * ks][0], sacc[2 * ks][1], phi[0], plo[0]);
            split2(sacc[2 * ks][2], sacc[2 * ks][3], phi[1], plo[1]);
            split2(sacc[2 * ks + 1][0], sacc[2 * ks + 1][1], phi[2], plo[2]);
            split2(sacc[2 * ks + 1][2], sacc[2 * ks + 1][3], phi[3], plo[3]);
#pragma unroll
            for (int dp = 0; dp < 8; dp++) {
                uint32_t vh4[4], vl4[4];
                int vr = ks * 16 + (lane & 7) + ((lane >> 3) & 1) * 8;
                int vc = dp * 2 + (lane >> 4);
                uint32_t off = swz256(vr, vc);
                ldsm_x4_t(vh4, stage + ST_VH + off);
                ldsm_x4_t(vl4, stage + ST_VL + off);
                mma16816(oacc[dp * 2], phi, vh4[0], vh4[1]);
                mma16816(oacc[dp * 2], phi, vl4[0], vl4[1]);
                mma16816(oacc[dp * 2], plo, vh4[0], vh4[1]);
                mma16816(oacc[dp * 2 + 1], phi, vh4[2], vh4[3]);
                mma16816(oacc[dp * 2 + 1], phi, vl4[2], vl4[3]);
                mma16816(oacc[dp * 2 + 1], plo, vh4[2], vh4[3]);
            }
        }
    }

    // ---- epilogue: write bf16 hi/lo ----
    float il0 = 1.0f / l0, il1 = 1.0f / l1;
    __nv_bfloat16* oh = ohi + ((size_t)(b * SS)) * QSTR + h * HD;
    __nv_bfloat16* ol = olo + ((size_t)(b * SS)) * QSTR + h * HD;
    int r0 = qb * 128 + warp_m + (lane >> 2);
#pragma unroll
    for (int nt = 0; nt < 16; nt++) {
        int dim = nt * 8 + (lane & 3) * 2;
        uint32_t h0, l0b, h1, l1b;
        split2(oacc[nt][0] * il0, oacc[nt][1] * il0, h0, l0b);
        split2(oacc[nt][2] * il1, oacc[nt][3] * il1, h1, l1b);
        *(uint32_t*)&oh[(size_t)r0 * QSTR + dim] = h0;
        *(uint32_t*)&ol[(size_t)r0 * QSTR + dim] = l0b;
        *(uint32_t*)&oh[(size_t)(r0 + 8) * QSTR + dim] = h1;
        *(uint32_t*)&ol[(size_t)(r0 + 8) * QSTR + dim] = l1b;
    }
}

// ---------------------------------------------------------------------------
extern "C" void kernel_launch(void* const* d_in, const int* in_sizes, int n_in,
                              void* d_out, int out_size)
{
    const float* hs  = (const float*)d_in[0];
    const float* q_w = (const float*)d_in[1];
    const float* k_w = (const float*)d_in[2];
    const float* v_w = (const float*)d_in[3];
    const float* o_w = (const float*)d_in[4];
    const float* qn  = (const float*)d_in[5];
    const float* kn  = (const float*)d_in[6];
    float* out = (float*)d_out;

    float *pq, *pk, *pv;
    __nv_bfloat16 *hsh, *hsl, *qwh, *qwl, *kwh, *kwl, *vwh, *vwl, *owh, *owl;
    __nv_bfloat16 *pqh, *pql, *pkh, *pkl, *pvh, *pvl, *pah, *pal;
    cudaGetSymbolAddress((void**)&pq, g_q);
    cudaGetSymbolAddress((void**)&pk, g_k);
    cudaGetSymbolAddress((void**)&pv, g_v);
    cudaGetSymbolAddress((void**)&hsh, g_hs_hi);
    cudaGetSymbolAddress((void**)&hsl, g_hs_lo);
    cudaGetSymbolAddress((void**)&qwh, g_qw_hi);
    cudaGetSymbolAddress((void**)&qwl, g_qw_lo);
    cudaGetSymbolAddress((void**)&kwh, g_kw_hi);
    cudaGetSymbolAddress((void**)&kwl, g_kw_lo);
    cudaGetSymbolAddress((void**)&vwh, g_vw_hi);
    cudaGetSymbolAddress((void**)&vwl, g_vw_lo);
    cudaGetSymbolAddress((void**)&owh, g_ow_hi);
    cudaGetSymbolAddress((void**)&owl, g_ow_lo);
    cudaGetSymbolAddress((void**)&pqh, g_qhi);
    cudaGetSymbolAddress((void**)&pql, g_qlo);
    cudaGetSymbolAddress((void**)&pkh, g_khi);
    cudaGetSymbolAddress((void**)&pkl, g_klo);
    cudaGetSymbolAddress((void**)&pvh, g_vhi);
    cudaGetSymbolAddress((void**)&pvl, g_vlo);
    cudaGetSymbolAddress((void**)&pah, g_ahi);
    cudaGetSymbolAddress((void**)&pal, g_alo);

    const int M = BB * SS;     // 4096
    const int K = HH;          // 2048
    const float RSCALE = 0.08838834764831845f;

    // pre-split operands to bf16 hi/lo
    split_f32<<<(M * HH) / 1024, 256>>>(hs, hsh, hsl);
    split_f32<<<(NH * HD * HH) / 1024, 256>>>(q_w, qwh, qwl);
    split_f32<<<(NKV * HD * HH) / 1024, 256>>>(k_w, kwh, kwl);
    split_f32<<<(NKV * HD * HH) / 1024, 256>>>(v_w, vwh, vwl);
    split_f32<<<(HH * NH * HD) / 1024, 256>>>(o_w, owh, owl);

    cudaFuncSetAttribute(gemm_bf16, cudaFuncAttributeMaxDynamicSharedMemorySize,
                         GS_SMEM);

    // QKV projections
    gemm_bf16<<<dim3((NH * HD) / 128, M / 128), 512, GS_SMEM>>>(hsh, hsl, qwh, qwl,
                                                                pq, M, NH * HD, K);
    gemm_bf16<<<dim3((NKV * HD) / 128, M / 128), 512, GS_SMEM>>>(hsh, hsl, kwh, kwl,
                                                                 pk, M, NKV * HD, K);
    gemm_bf16<<<dim3((NKV * HD) / 128, M / 128), 512, GS_SMEM>>>(hsh, hsl, vwh, vwl,
                                                                 pv, M, NKV * HD, K);

    // RMSNorm + RoPE -> bf16 hi/lo (Q pre-scaled); V split
    rmsnorm_rope<<<dim3(M, NH), 128>>>(pq, qn, pqh, pql, NH, RSCALE);
    rmsnorm_rope<<<dim3(M, NKV), 128>>>(pk, kn, pkh, pkl, NKV, 1.0f);
    split_f32<<<(M * NKV * HD) / 1024, 256>>>(pv, pvh, pvl);

    // tensor-core causal flash attention (GQA), double-buffered K/V
    cudaFuncSetAttribute(flash_attn_tc, cudaFuncAttributeMaxDynamicSharedMemorySize,
                         FL_SMEM);
    flash_attn_tc<<<dim3(SS / 128, NH, BB), 256, FL_SMEM>>>(pqh, pql, pkh, pkl,
                                                            pvh, pvl, pah, pal);

    // output projection
    gemm_bf16<<<dim3(HH / 128, M / 128), 512, GS_SMEM>>>(pah, pal, owh, owl,
                                                         out, M, HH, K);
}

// round 8
// speedup vs baseline: 4.0427x; 1.1918x over previous
#include <cuda_runtime.h>
#include <cuda_bf16.h>
#include <cuda_fp16.h>
#include <stdint.h>
#include <math.h>

#define BB 2
#define SS 2048
#define HH 2048
#define NH 16
#define NKV 4
#define HD 128

// ---------------- scratch (device globals: allocation-free) ----------------
__device__ float g_q[(size_t)BB * SS * NH * HD];
__device__ float g_k[(size_t)BB * SS * NKV * HD];
__device__ float g_v[(size_t)BB * SS * NKV * HD];
// fp16 split GEMM operands (A side: hi+lo; B side: hi only)
__device__ __half g_hs_hi[(size_t)BB * SS * HH];
__device__ __half g_hs_lo[(size_t)BB * SS * HH];
__device__ __half g_qw_hi[(size_t)NH * HD * HH];
__device__ __half g_kw_hi[(size_t)NKV * HD * HH];
__device__ __half g_vw_hi[(size_t)NKV * HD * HH];
__device__ __half g_ow_hi[(size_t)HH * NH * HD];
// post-norm attention operands (bf16 3-pass, unchanged numerics)
__device__ __nv_bfloat16 g_qhi[(size_t)BB * SS * NH * HD];
__device__ __nv_bfloat16 g_qlo[(size_t)BB * SS * NH * HD];
__device__ __nv_bfloat16 g_khi[(size_t)BB * SS * NKV * HD];
__device__ __nv_bfloat16 g_klo[(size_t)BB * SS * NKV * HD];
__device__ __nv_bfloat16 g_vhi[(size_t)BB * SS * NKV * HD];
__device__ __nv_bfloat16 g_vlo[(size_t)BB * SS * NKV * HD];
// attention output (fp16 hi/lo, feeds O projection)
__device__ __half g_ahi[(size_t)BB * SS * NH * HD];
__device__ __half g_alo[(size_t)BB * SS * NH * HD];

// ===================== warp-MMA helpers =====================
__device__ __forceinline__ uint32_t smem_to_u32(const void* p) {
    uint32_t a;
    asm("{ .reg .u64 t; cvta.to.shared.u64 t, %1; cvt.u32.u64 %0, t; }"
        : "=r"(a) : "l"(p));
    return a;
}
__device__ __forceinline__ void ldsm_x4(uint32_t r[4], uint32_t addr) {
    asm volatile("ldmatrix.sync.aligned.m8n8.x4.shared.b16 {%0,%1,%2,%3}, [%4];"
                 : "=r"(r[0]), "=r"(r[1]), "=r"(r[2]), "=r"(r[3]) : "r"(addr));
}
__device__ __forceinline__ void ldsm_x4_t(uint32_t r[4], uint32_t addr) {
    asm volatile("ldmatrix.sync.aligned.m8n8.x4.trans.shared.b16 {%0,%1,%2,%3}, [%4];"
                 : "=r"(r[0]), "=r"(r[1]), "=r"(r[2]), "=r"(r[3]) : "r"(addr));
}
// bf16 MMA (attention)
__device__ __forceinline__ void mma16816(float c[4], const uint32_t a[4],
                                         const uint32_t b0, const uint32_t b1) {
    asm volatile(
        "mma.sync.aligned.m16n8k16.row.col.f32.bf16.bf16.f32 "
        "{%0,%1,%2,%3}, {%4,%5,%6,%7}, {%8,%9}, {%0,%1,%2,%3};"
        : "+f"(c[0]), "+f"(c[1]), "+f"(c[2]), "+f"(c[3])
        : "r"(a[0]), "r"(a[1]), "r"(a[2]), "r"(a[3]), "r"(b0), "r"(b1));
}
// fp16 MMA (projections)
__device__ __forceinline__ void mma16816h(float c[4], const uint32_t a[4],
                                          const uint32_t b0, const uint32_t b1) {
    asm volatile(
        "mma.sync.aligned.m16n8k16.row.col.f32.f16.f16.f32 "
        "{%0,%1,%2,%3}, {%4,%5,%6,%7}, {%8,%9}, {%0,%1,%2,%3};"
        : "+f"(c[0]), "+f"(c[1]), "+f"(c[2]), "+f"(c[3])
        : "r"(a[0]), "r"(a[1]), "r"(a[2]), "r"(a[3]), "r"(b0), "r"(b1));
}
__device__ __forceinline__ void cp_async16(uint32_t dst, const void* src) {
    asm volatile("cp.async.cg.shared.global [%0], [%1], 16;"
                 :: "r"(dst), "l"(src) : "memory");
}
#define CP_COMMIT() asm volatile("cp.async.commit_group;" ::: "memory")
#define CP_WAIT(n)  asm volatile("cp.async.wait_group %0;" :: "n"(n) : "memory")

// bf16 split (attention path)
__device__ __forceinline__ void split2(float x, float y, uint32_t& hi, uint32_t& lo) {
    __nv_bfloat16 hx = __float2bfloat16_rn(x);
    __nv_bfloat16 hy = __float2bfloat16_rn(y);
    __nv_bfloat16 lx = __float2bfloat16_rn(x - __bfloat162float(hx));
    __nv_bfloat16 ly = __float2bfloat16_rn(y - __bfloat162float(hy));
    hi = (uint32_t)__bfloat16_as_ushort(hx) | ((uint32_t)__bfloat16_as_ushort(hy) << 16);
    lo = (uint32_t)__bfloat16_as_ushort(lx) | ((uint32_t)__bfloat16_as_ushort(ly) << 16);
}
// fp16 split (GEMM path)
__device__ __forceinline__ void split2h(float x, float y, uint32_t& hi, uint32_t& lo) {
    __half hx = __float2half_rn(x);
    __half hy = __float2half_rn(y);
    __half lx = __float2half_rn(x - __half2float(hx));
    __half ly = __float2half_rn(y - __half2float(hy));
    hi = (uint32_t)__half_as_ushort(hx) | ((uint32_t)__half_as_ushort(hy) << 16);
    lo = (uint32_t)__half_as_ushort(lx) | ((uint32_t)__half_as_ushort(ly) << 16);
}

// swizzled byte offset in a [rows x 32 elems] 16-bit tile (64B rows, 4x16B units)
__device__ __forceinline__ uint32_t swz(int row, int c) {
    return (uint32_t)(row * 64 + ((c ^ ((row >> 1) & 3)) << 4));
}
// swizzled byte offset in a [rows x 128 elems] 16-bit tile (256B rows, 16x16B units)
__device__ __forceinline__ uint32_t swz256(int row, int c) {
    return (uint32_t)(row * 256 + ((c ^ (row & 7)) << 4));
}

// ---------------------------------------------------------------------------
// elementwise converters
// ---------------------------------------------------------------------------
__global__ void split_f32h(const float* __restrict__ x,
                           __half* __restrict__ hi, __half* __restrict__ lo)
{
    size_t i = ((size_t)blockIdx.x * blockDim.x + threadIdx.x) * 4;
    float4 f = *(const float4*)(x + i);
    uint2 h, l;
    split2h(f.x, f.y, h.x, l.x);
    split2h(f.z, f.w, h.y, l.y);
    *(uint2*)(hi + i) = h;
    *(uint2*)(lo + i) = l;
}
__global__ void conv_f32h(const float* __restrict__ x, __half* __restrict__ hi)
{
    size_t i = ((size_t)blockIdx.x * blockDim.x + threadIdx.x) * 4;
    float4 f = *(const float4*)(x + i);
    uint2 h;
    h.x = (uint32_t)__half_as_ushort(__float2half_rn(f.x))
        | ((uint32_t)__half_as_ushort(__float2half_rn(f.y)) << 16);
    h.y = (uint32_t)__half_as_ushort(__float2half_rn(f.z))
        | ((uint32_t)__half_as_ushort(__float2half_rn(f.w)) << 16);
    *(uint2*)(hi + i) = h;
}
__global__ void split_f32b(const float* __restrict__ x,
                           __nv_bfloat16* __restrict__ hi,
                           __nv_bfloat16* __restrict__ lo)
{
    size_t i = ((size_t)blockIdx.x * blockDim.x + threadIdx.x) * 4;
    float4 f = *(const float4*)(x + i);
    uint2 h, l;
    split2(f.x, f.y, h.x, l.x);
    split2(f.z, f.w, h.y, l.y);
    *(uint2*)(hi + i) = h;
    *(uint2*)(lo + i) = l;
}

// ---------------------------------------------------------------------------
// fp16 2-pass split GEMM: C[M][N] = (Ahi+Alo)[M][K] * Bhi[N][K]^T (fp32 out)
// BM=BN=128, BK=32, 512 threads (16 warps 4x4), warp tile 32x32.
// 3-stage cp.async pipeline; 24KB/stage.
// ---------------------------------------------------------------------------
#define GS_AH 0
#define GS_AL 8192
#define GS_BH 16384
#define GS_STAGE 24576
#define GS_SMEM (3 * GS_STAGE)

__global__ void __launch_bounds__(512) gemm_fp16(
    const __half* __restrict__ Ahi, const __half* __restrict__ Alo,
    const __half* __restrict__ Bhi,
    float* __restrict__ C, int M, int N, int K)
{
    extern __shared__ char smem[];
    const uint32_t sb = smem_to_u32(smem);

    const int t = threadIdx.x;
    const int lane = t & 31, wid = t >> 5;
    const int bm = blockIdx.y * 128, bn = blockIdx.x * 128;
    const int wm = (wid & 3) * 32;
    const int wn = (wid >> 2) * 32;

    const int lrow = t >> 2, lc = t & 3;
    const size_t ga = (size_t)(bm + lrow) * K + lc * 8;
    const size_t gb = (size_t)(bn + lrow) * K + lc * 8;
    const uint32_t st = swz(lrow, lc);
    const int nch = K >> 5;

    auto issue = [&](int ch) {
        uint32_t base = sb + (uint32_t)(ch % 3) * GS_STAGE + st;
        size_t ka = ga + (size_t)ch * 32;
        size_t kb = gb + (size_t)ch * 32;
        cp_async16(base + GS_AH, Ahi + ka);
        cp_async16(base + GS_AL, Alo + ka);
        cp_async16(base + GS_BH, Bhi + kb);
    };

    issue(0); CP_COMMIT();
    issue(1); CP_COMMIT();

    float acc[2][4][4];
#pragma unroll
    for (int i = 0; i < 2; i++)
#pragma unroll
        for (int j = 0; j < 4; j++)
#pragma unroll
            for (int q = 0; q < 4; q++) acc[i][j][q] = 0.0f;

    for (int ch = 0; ch < nch; ch++) {
        CP_WAIT(1);
        __syncthreads();
        if (ch + 2 < nch) issue(ch + 2);
        CP_COMMIT();

        const uint32_t base = sb + (uint32_t)(ch % 3) * GS_STAGE;
#pragma unroll
        for (int ks = 0; ks < 2; ks++) {
            uint32_t ah[2][4], al[2][4];
#pragma unroll
            for (int mt = 0; mt < 2; mt++) {
                int row = wm + mt * 16 + (lane & 15);
                int c = ks * 2 + (lane >> 4);
                uint32_t off = swz(row, c);
                ldsm_x4(ah[mt], base + GS_AH + off);
                ldsm_x4(al[mt], base + GS_AL + off);
            }
#pragma unroll
            for (int np = 0; np < 2; np++) {
                uint32_t bh[4];
                int row = wn + np * 16 + (lane & 7) + ((lane >> 4) & 1) * 8;
                int c = ks * 2 + ((lane >> 3) & 1);
                uint32_t off = swz(row, c);
                ldsm_x4(bh, base + GS_BH + off);
#pragma unroll
                for (int half = 0; half < 2; half++) {
                    int nt = np * 2 + half, pb = half * 2;
#pragma unroll
                    for (int mt = 0; mt < 2; mt++) {
                        mma16816h(acc[mt][nt], ah[mt], bh[pb], bh[pb + 1]);
                        mma16816h(acc[mt][nt], al[mt], bh[pb], bh[pb + 1]);
                    }
                }
            }
        }
        __syncthreads();
    }

#pragma unroll
    for (int mt = 0; mt < 2; mt++)
#pragma unroll
        for (int nt = 0; nt < 4; nt++) {
            int r0 = bm + wm + mt * 16 + (lane >> 2);
            int c0 = bn + wn + nt * 8 + (lane & 3) * 2;
            float2 v0 = make_float2(acc[mt][nt][0], acc[mt][nt][1]);
            float2 v1 = make_float2(acc[mt][nt][2], acc[mt][nt][3]);
            *(float2*)&C[(size_t)r0 * N + c0] = v0;
            *(float2*)&C[(size_t)(r0 + 8) * N + c0] = v1;
        }
}

// ---------------------------------------------------------------------------
// Fused per-head RMSNorm + RoPE -> split bf16 hi/lo (optionally pre-scaled).
// ---------------------------------------------------------------------------
__global__ void rmsnorm_rope(const float* __restrict__ x, const float* __restrict__ w,
                             __nv_bfloat16* __restrict__ hi, __nv_bfloat16* __restrict__ lo,
                             int nheads, float prescale)
{
    const int row = blockIdx.x;
    const int h   = blockIdx.y;
    const int s   = row & (SS - 1);
    const int d   = threadIdx.x;

    const size_t base = ((size_t)row * nheads + h) * HD;
    float val = x[base + d];

    float ss = val * val;
#pragma unroll
    for (int off = 16; off > 0; off >>= 1)
        ss += __shfl_xor_sync(0xffffffffu, ss, off);

    __shared__ float red[4];
    __shared__ float xs[128];
    const int warp = d >> 5, lane = d & 31;
    if (lane == 0) red[warp] = ss;
    __syncthreads();
    float tot = red[0] + red[1] + red[2] + red[3];
    float xn  = val * rsqrtf(tot * (1.0f / 128.0f) + 1e-5f) * w[d];
    xs[d] = xn;
    __syncthreads();

    const int i = d & 63;
    float inv_freq = expf(-(float)i * (13.122363377404328f / 64.0f));
    float ang = (float)s * inv_freq;
    float sn, cs;
    sincosf(ang, &sn, &cs);

    float other = xs[d ^ 64];
    float res = (d < 64) ? (xn * cs - other * sn) : (xn * cs + other * sn);
    res *= prescale;

    __nv_bfloat16 hb = __float2bfloat16_rn(res);
    __nv_bfloat16 lb = __float2bfloat16_rn(res - __bfloat162float(hb));
    hi[base + d] = hb;
    lo[base + d] = lb;
}

// ---------------------------------------------------------------------------
// Tensor-core causal flash attention, split-bf16 (3-pass), GQA.
// BM=128, BN=64, D=128. 256 threads = 8 warps; warp tile m16 x n64.
// K/V double-buffered via cp.async. qb reversed for wave balance.
// Epilogue writes fp16 hi/lo (feeds fp16 O projection).
// ---------------------------------------------------------------------------
#define SQ_HI 0
#define SQ_LO 32768
#define KV_BASE 65536
#define KV_STAGE 65536
#define ST_KH 0
#define ST_KL 16384
#define ST_VH 32768
#define ST_VL 49152
#define FL_SMEM (KV_BASE + 2 * KV_STAGE)

__global__ void __launch_bounds__(256) flash_attn_tc(
    const __nv_bfloat16* __restrict__ qhi, const __nv_bfloat16* __restrict__ qlo,
    const __nv_bfloat16* __restrict__ khi, const __nv_bfloat16* __restrict__ klo,
    const __nv_bfloat16* __restrict__ vhi, const __nv_bfloat16* __restrict__ vlo,
    __half* __restrict__ ohi, __half* __restrict__ olo)
{
    extern __shared__ char smem[];
    const uint32_t sb = smem_to_u32(smem);
    const int t = threadIdx.x, lane = t & 31, wid = t >> 5;
    const int qb = gridDim.x - 1 - blockIdx.x;   // heavy blocks first
    const int h = blockIdx.y, b = blockIdx.z;
    const int kvh = h >> 2;
    const int warp_m = wid * 16;
    const int QSTR = NH * HD;
    const int KSTR = NKV * HD;

    const int cr = t >> 4, cc = t & 15;
    const __nv_bfloat16* kh0 = khi + ((size_t)(b * SS)) * KSTR + kvh * HD;
    const __nv_bfloat16* kl0 = klo + ((size_t)(b * SS)) * KSTR + kvh * HD;
    const __nv_bfloat16* vh0 = vhi + ((size_t)(b * SS)) * KSTR + kvh * HD;
    const __nv_bfloat16* vl0 = vlo + ((size_t)(b * SS)) * KSTR + kvh * HD;

    auto issue_kv = [&](int kb) {
        uint32_t stage = sb + KV_BASE + (uint32_t)(kb & 1) * KV_STAGE;
#pragma unroll
        for (int i = 0; i < 4; i++) {
            int r = cr + i * 16;
            size_t g = (size_t)(kb * 64 + r) * KSTR + cc * 8;
            uint32_t s = swz256(r, cc);
            cp_async16(stage + ST_KH + s, kh0 + g);
            cp_async16(stage + ST_KL + s, kl0 + g);
            cp_async16(stage + ST_VH + s, vh0 + g);
            cp_async16(stage + ST_VL + s, vl0 + g);
        }
    };

    issue_kv(0); CP_COMMIT();

    {
        const __nv_bfloat16* qh = qhi + ((size_t)(b * SS + qb * 128)) * QSTR + h * HD;
        const __nv_bfloat16* ql = qlo + ((size_t)(b * SS + qb * 128)) * QSTR + h * HD;
#pragma unroll
        for (int i = 0; i < 8; i++) {
            int u = t + i * 256;
            int r = u >> 4, c = u & 15;
            size_t g = (size_t)r * QSTR + c * 8;
            uint32_t s = swz256(r, c);
            *(uint4*)(smem + SQ_HI + s) = *(const uint4*)(qh + g);
            *(uint4*)(smem + SQ_LO + s) = *(const uint4*)(ql + g);
        }
    }

    float m0 = -INFINITY, m1 = -INFINITY, l0 = 0.0f, l1 = 0.0f;
    float oacc[16][4];
#pragma unroll
    for (int i = 0; i < 16; i++)
#pragma unroll
        for (int j = 0; j < 4; j++) oacc[i][j] = 0.0f;

    const int row_lo = qb * 128 + warp_m + (lane >> 2);
    const int nkb = 2 * qb + 2;

    for (int kb = 0; kb < nkb; kb++) {
        __syncthreads();
        if (kb + 1 < nkb) {
            issue_kv(kb + 1); CP_COMMIT();
            CP_WAIT(1);
        } else {
            CP_WAIT(0);
        }
        __syncthreads();

        if (kb * 64 > qb * 128 + warp_m + 15) continue;
        const bool need_mask = (kb * 64 + 63 > qb * 128 + warp_m);
        const uint32_t stage = sb + KV_BASE + (uint32_t)(kb & 1) * KV_STAGE;

        float sacc[8][4];
#pragma unroll
        for (int i = 0; i < 8; i++)
#pragma unroll
            for (int j = 0; j < 4; j++) sacc[i][j] = 0.0f;

#pragma unroll
        for (int ks = 0; ks < 8; ks++) {
            uint32_t ah[4], al[4];
            {
                int ar = warp_m + (lane & 15);
                int ac = ks * 2 + (lane >> 4);
                uint32_t off = swz256(ar, ac);
                ldsm_x4(ah, sb + SQ_HI + off);
                ldsm_x4(al, sb + SQ_LO + off);
            }
#pragma unroll
            for (int np = 0; np < 4; np++) {
                uint32_t bh[4], bl[4];
                int br = np * 16 + (lane & 7) + ((lane >> 4) & 1) * 8;
                int bc = ks * 2 + ((lane >> 3) & 1);
                uint32_t off = swz256(br, bc);
                ldsm_x4(bh, stage + ST_KH + off);
                ldsm_x4(bl, stage + ST_KL + off);
#pragma unroll
                for (int half = 0; half < 2; half++) {
                    int nt = np * 2 + half, pb = half * 2;
                    mma16816(sacc[nt], ah, bh[pb], bh[pb + 1]);
                    mma16816(sacc[nt], ah, bl[pb], bl[pb + 1]);
                    mma16816(sacc[nt], al, bh[pb], bh[pb + 1]);
                }
            }
        }

        if (need_mask) {
#pragma unroll
            for (int nt = 0; nt < 8; nt++) {
                int col = kb * 64 + nt * 8 + (lane & 3) * 2;
#pragma unroll
                for (int j = 0; j < 4; j++) {
                    int cc2 = col + (j & 1);
                    int rr = row_lo + ((j >> 1) << 3);
                    if (cc2 > rr) sacc[nt][j] = -INFINITY;
                }
            }
        }

        float mt0 = -INFINITY, mt1 = -INFINITY;
#pragma unroll
        for (int nt = 0; nt < 8; nt++) {
            mt0 = fmaxf(mt0, fmaxf(sacc[nt][0], sacc[nt][1]));
            mt1 = fmaxf(mt1, fmaxf(sacc[nt][2], sacc[nt][3]));
        }
        mt0 = fmaxf(mt0, __shfl_xor_sync(0xffffffffu, mt0, 1));
        mt0 = fmaxf(mt0, __shfl_xor_sync(0xffffffffu, mt0, 2));
        mt1 = fmaxf(mt1, __shfl_xor_sync(0xffffffffu, mt1, 1));
        mt1 = fmaxf(mt1, __shfl_xor_sync(0xffffffffu, mt1, 2));

        float mn0 = fmaxf(m0, mt0), mn1 = fmaxf(m1, mt1);
        float sc0 = __expf(m0 - mn0), sc1 = __expf(m1 - mn1);
        m0 = mn0; m1 = mn1;

        float ps0 = 0.0f, ps1 = 0.0f;
#pragma unroll
        for (int nt = 0; nt < 8; nt++) {
            sacc[nt][0] = __expf(sacc[nt][0] - mn0);
            sacc[nt][1] = __expf(sacc[nt][1] - mn0);
            sacc[nt][2] = __expf(sacc[nt][2] - mn1);
            sacc[nt][3] = __expf(sacc[nt][3] - mn1);
            ps0 += sacc[nt][0] + sacc[nt][1];
            ps1 += sacc[nt][2] + sacc[nt][3];
        }
        ps0 += __shfl_xor_sync(0xffffffffu, ps0, 1);
        ps0 += __shfl_xor_sync(0xffffffffu, ps0, 2);
        ps1 += __shfl_xor_sync(0xffffffffu, ps1, 1);
        ps1 += __shfl_xor_sync(0xffffffffu, ps1, 2);
        l0 = l0 * sc0 + ps0;
        l1 = l1 * sc1 + ps1;

#pragma unroll
        for (int nt = 0; nt < 16; nt++) {
            oacc[nt][0] *= sc0; oacc[nt][1] *= sc0;
            oacc[nt][2] *= sc1; oacc[nt][3] *= sc1;
        }

#pragma unroll
        for (int ks = 0; ks < 4; ks++) {
            uint32_t phi[4], plo[4];
            split2(sacc[2 * ks][0], sacc[2 * ks][1], phi[0], plo[0]);
            split2(sacc[2 * ks][2], sacc[2 * ks][3], phi[1], plo[1]);
            split2(sacc[2 * ks + 1][0], sacc[2 * ks + 1][1], phi[2], plo[2]);
            split2(sacc[2 * ks + 1][2], sacc[2 * ks + 1][3], phi[3], plo[3]);
#pragma unroll
            for (int dp = 0; dp < 8; dp++) {
                uint32_t vh4[4], vl4[4];
                int vr = ks * 16 + (lane & 7) + ((lane >> 3) & 1) * 8;
                int vc = dp * 2 + (lane >> 4);
                uint32_t off = swz256(vr, vc);
                ldsm_x4_t(vh4, stage + ST_VH + off);
                ldsm_x4_t(vl4, stage + ST_VL + off);
                mma16816(oacc[dp * 2], phi, vh4[0], vh4[1]);
                mma16816(oacc[dp * 2], phi, vl4[0], vl4[1]);
                mma16816(oacc[dp * 2], plo, vh4[0], vh4[1]);
                mma16816(oacc[dp * 2 + 1], phi, vh4[2], vh4[3]);
                mma16816(oacc[dp * 2 + 1], phi, vl4[2], vl4[3]);
                mma16816(oacc[dp * 2 + 1], plo, vh4[2], vh4[3]);
            }
        }
    }

    // ---- epilogue: write fp16 hi/lo ----
    float il0 = 1.0f / l0, il1 = 1.0f / l1;
    __half* oh = ohi + ((size_t)(b * SS)) * QSTR + h * HD;
    __half* ol = olo + ((size_t)(b * SS)) * QSTR + h * HD;
    int r0 = qb * 128 + warp_m + (lane >> 2);
#pragma unroll
    for (int nt = 0; nt < 16; nt++) {
        int dim = nt * 8 + (lane & 3) * 2;
        uint32_t h0, l0b, h1, l1b;
        split2h(oacc[nt][0] * il0, oacc[nt][1] * il0, h0, l0b);
        split2h(oacc[nt][2] * il1, oacc[nt][3] * il1, h1, l1b);
        *(uint32_t*)&oh[(size_t)r0 * QSTR + dim] = h0;
        *(uint32_t*)&ol[(size_t)r0 * QSTR + dim] = l0b;
        *(uint32_t*)&oh[(size_t)(r0 + 8) * QSTR + dim] = h1;
        *(uint32_t*)&ol[(size_t)(r0 + 8) * QSTR + dim] = l1b;
    }
}

// ---------------------------------------------------------------------------
extern "C" void kernel_launch(void* const* d_in, const int* in_sizes, int n_in,
                              void* d_out, int out_size)
{
    const float* hs  = (const float*)d_in[0];
    const float* q_w = (const float*)d_in[1];
    const float* k_w = (const float*)d_in[2];
    const float* v_w = (const float*)d_in[3];
    const float* o_w = (const float*)d_in[4];
    const float* qn  = (const float*)d_in[5];
    const float* kn  = (const float*)d_in[6];
    float* out = (float*)d_out;

    float *pq, *pk, *pv;
    __half *hsh, *hsl, *qwh, *kwh, *vwh, *owh, *pah, *pal;
    __nv_bfloat16 *pqh, *pql, *pkh, *pkl, *pvh, *pvl;
    cudaGetSymbolAddress((void**)&pq, g_q);
    cudaGetSymbolAddress((void**)&pk, g_k);
    cudaGetSymbolAddress((void**)&pv, g_v);
    cudaGetSymbolAddress((void**)&hsh, g_hs_hi);
    cudaGetSymbolAddress((void**)&hsl, g_hs_lo);
    cudaGetSymbolAddress((void**)&qwh, g_qw_hi);
    cudaGetSymbolAddress((void**)&kwh, g_kw_hi);
    cudaGetSymbolAddress((void**)&vwh, g_vw_hi);
    cudaGetSymbolAddress((void**)&owh, g_ow_hi);
    cudaGetSymbolAddress((void**)&pah, g_ahi);
    cudaGetSymbolAddress((void**)&pal, g_alo);
    cudaGetSymbolAddress((void**)&pqh, g_qhi);
    cudaGetSymbolAddress((void**)&pql, g_qlo);
    cudaGetSymbolAddress((void**)&pkh, g_khi);
    cudaGetSymbolAddress((void**)&pkl, g_klo);
    cudaGetSymbolAddress((void**)&pvh, g_vhi);
    cudaGetSymbolAddress((void**)&pvl, g_vlo);

    const int M = BB * SS;     // 4096
    const int K = HH;          // 2048
    const float RSCALE = 0.08838834764831845f;

    // operand conversion: A sides hi+lo fp16, weights hi-only fp16
    split_f32h<<<(M * HH) / 1024, 256>>>(hs, hsh, hsl);
    conv_f32h<<<(NH * HD * HH) / 1024, 256>>>(q_w, qwh);
    conv_f32h<<<(NKV * HD * HH) / 1024, 256>>>(k_w, kwh);
    conv_f32h<<<(NKV * HD * HH) / 1024, 256>>>(v_w, vwh);
    conv_f32h<<<(HH * NH * HD) / 1024, 256>>>(o_w, owh);

    cudaFuncSetAttribute(gemm_fp16, cudaFuncAttributeMaxDynamicSharedMemorySize,
                         GS_SMEM);

    // QKV projections (fp16 2-pass)
    gemm_fp16<<<dim3((NH * HD) / 128, M / 128), 512, GS_SMEM>>>(hsh, hsl, qwh,
                                                                pq, M, NH * HD, K);
    gemm_fp16<<<dim3((NKV * HD) / 128, M / 128), 512, GS_SMEM>>>(hsh, hsl, kwh,
                                                                 pk, M, NKV * HD, K);
    gemm_fp16<<<dim3((NKV * HD) / 128, M / 128), 512, GS_SMEM>>>(hsh, hsl, vwh,
                                                                 pv, M, NKV * HD, K);

    // RMSNorm + RoPE -> bf16 hi/lo (Q pre-scaled); V split to bf16
    rmsnorm_rope<<<dim3(M, NH), 128>>>(pq, qn, pqh, pql, NH, RSCALE);
    rmsnorm_rope<<<dim3(M, NKV), 128>>>(pk, kn, pkh, pkl, NKV, 1.0f);
    split_f32b<<<(M * NKV * HD) / 1024, 256>>>(pv, pvh, pvl);

    // tensor-core causal flash attention (bf16 3-pass), fp16 hi/lo out
    cudaFuncSetAttribute(flash_attn_tc, cudaFuncAttributeMaxDynamicSharedMemorySize,
                         FL_SMEM);
    flash_attn_tc<<<dim3(SS / 128, NH, BB), 256, FL_SMEM>>>(pqh, pql, pkh, pkl,
                                                            pvh, pvl, pah, pal);

    // output projection (fp16 2-pass)
    gemm_fp16<<<dim3(HH / 128, M / 128), 512, GS_SMEM>>>(pah, pal, owh,
                                                         out, M, HH, K);
}